// round 14
// baseline (speedup 1.0000x reference)
#include <cuda_runtime.h>
#include <cuda_bf16.h>
#include <math.h>
#include <stdint.h>

// ---------------- problem constants ----------------
#define DD      128
#define HH      256
#define MAXN    8192
#define NB      64
#define MTHR    256

// scratch
__device__ float g_messages[2ull * MAXN * HH];
__device__ float g_p1[2ull * MAXN * HH];       // x @ W1[0:128]   per node
__device__ float g_p2[2ull * MAXN * HH];       // x @ W1[128:256] per node
__device__ float g_att[2ull * MAXN * DD];
__device__ float g_colmeans[2 * DD];
__device__ int   g_seg[2 * NB * 2];

// all weights as K=32 slices, row stride 80 B (32 data cols + 8 pad)
#define MB_SLICE 20480            // 256 n-rows * 80
#define MB_SLICE2 10240           // 128 n-rows * 80
__device__ __align__(16) unsigned char g_wtile[2][8][2][MB_SLICE];   // msg W1/W2
__device__ __align__(16) unsigned char g_uw1s[16][2][MB_SLICE];      // upd W1 (K=512)
__device__ __align__(16) unsigned char g_uw2s[8][2][MB_SLICE2];      // upd W2 (K=256, 128 outs)

// ---------------- PTX helpers ----------------
__device__ __forceinline__ uint32_t smem_u32(const void* p) {
    uint32_t a;
    asm("{ .reg .u64 t; cvta.to.shared.u64 t, %1; cvt.u32.u64 %0, t; }" : "=r"(a) : "l"(p));
    return a;
}
__device__ __forceinline__ void cp_async16(unsigned int saddr, const void* gptr) {
    asm volatile("cp.async.cg.shared.global [%0], [%1], 16;" :: "r"(saddr), "l"(gptr));
}
__device__ __forceinline__ void cp_commit() { asm volatile("cp.async.commit_group;"); }
template<int N>
__device__ __forceinline__ void cp_wait() { asm volatile("cp.async.wait_group %0;" :: "n"(N)); }
__device__ __forceinline__ void red_add_v2(float* p, float a, float b) {
    asm volatile("red.global.add.v2.f32 [%0], {%1,%2};" :: "l"(p), "f"(a), "f"(b) : "memory");
}
__device__ __forceinline__ void ldmx4(uint32_t r[4], uint32_t addr) {
    asm volatile("ldmatrix.sync.aligned.m8n8.x4.shared.b16 {%0,%1,%2,%3}, [%4];"
        : "=r"(r[0]), "=r"(r[1]), "=r"(r[2]), "=r"(r[3]) : "r"(addr));
}
__device__ __forceinline__ void mma_bf16(float d[4], const uint32_t a[4],
                                         uint32_t b0, uint32_t b1) {
    asm volatile("mma.sync.aligned.m16n8k16.row.col.f32.bf16.bf16.f32 "
        "{%0,%1,%2,%3}, {%4,%5,%6,%7}, {%8,%9}, {%0,%1,%2,%3};"
        : "+f"(d[0]), "+f"(d[1]), "+f"(d[2]), "+f"(d[3])
        : "r"(a[0]), "r"(a[1]), "r"(a[2]), "r"(a[3]), "r"(b0), "r"(b1));
}
__device__ __forceinline__ uint32_t pk(__nv_bfloat16 a, __nv_bfloat16 b) {
    __nv_bfloat162 t = __halves2bfloat162(a, b);
    return *reinterpret_cast<uint32_t*>(&t);
}

// ---------------- tiny setup kernels ----------------
__global__ void zero_msgs_kernel(int n4) {
    int i = blockIdx.x * blockDim.x + threadIdx.x;
    if (i < n4) ((float4*)g_messages)[i] = make_float4(0.f, 0.f, 0.f, 0.f);
}

__global__ void seg_kernel(const int* __restrict__ b1, const int* __restrict__ b2, int N) {
    int t = threadIdx.x;
    if (t >= 2 * NB) return;
    int g = t / NB, b = t % NB;
    const int* arr = g ? b2 : b1;
    int lo = 0, hi = N;
    while (lo < hi) { int m = (lo + hi) >> 1; if (arr[m] < b) lo = m + 1; else hi = m; }
    int start = lo;
    lo = 0; hi = N;
    while (lo < hi) { int m = (lo + hi) >> 1; if (arr[m] <= b) lo = m + 1; else hi = m; }
    g_seg[t * 2 + 0] = start;
    g_seg[t * 2 + 1] = lo;
}

__global__ void colmean_kernel(const float* __restrict__ x1, const float* __restrict__ x2, int N) {
    const float* x = blockIdx.x ? x2 : x1;
    int c = threadIdx.x;
    float s0 = 0.f, s1 = 0.f, s2 = 0.f, s3 = 0.f;
    int r = 0;
    for (; r + 3 < N; r += 4) {
        s0 += x[(size_t)(r + 0) * DD + c];
        s1 += x[(size_t)(r + 1) * DD + c];
        s2 += x[(size_t)(r + 2) * DD + c];
        s3 += x[(size_t)(r + 3) * DD + c];
    }
    for (; r < N; ++r) s0 += x[(size_t)r * DD + c];
    g_colmeans[blockIdx.x * DD + c] = (s0 + s1 + s2 + s3) * (1.f / (float)N);
}

__device__ __forceinline__ void split_store(unsigned char* hdst, unsigned char* ldst,
                                            size_t off, float w) {
    __nv_bfloat16 h = __float2bfloat16(w);
    __nv_bfloat16 l = __float2bfloat16(w - __bfloat162float(h));
    *(__nv_bfloat16*)(hdst + off) = h;
    *(__nv_bfloat16*)(ldst + off) = l;
}

// merged weight prep: msg W1/W2 (131072), upd W1 (131072), upd W2 (32768)
__global__ void prep_all_kernel(const float* __restrict__ mW1, const float* __restrict__ mW2,
                                const float* __restrict__ uW1, const float* __restrict__ uW2) {
    int idx = blockIdx.x * 256 + threadIdx.x;
    if (idx < 131072) {
        int layer = idx >> 16;
        int e = idx & 65535;
        int k = e >> 8, n = e & 255;
        const float* W = layer ? mW2 : mW1;
        split_store(g_wtile[layer][k >> 5][0], g_wtile[layer][k >> 5][1],
                    (size_t)n * 80 + (size_t)(k & 31) * 2, W[e]);
    } else if (idx < 262144) {
        int e = idx - 131072;
        int k = e >> 8, n = e & 255;         // k in [0,512)
        split_store(g_uw1s[k >> 5][0], g_uw1s[k >> 5][1],
                    (size_t)n * 80 + (size_t)(k & 31) * 2, uW1[e]);
    } else {
        int e = idx - 262144;
        int k = e >> 7, n = e & 127;         // k in [0,256)
        split_store(g_uw2s[k >> 5][0], g_uw2s[k >> 5][1],
                    (size_t)n * 80 + (size_t)(k & 31) * 2, uW2[e]);
    }
}

// ================= shared mma pieces (256 thr, occ 2) =================
#define MA_STRIDE 528
#define MOFF_AH 0
#define MOFF_AL 33792
#define MOFF_B  67584
#define MOFF_BIAS 108544
#define MOFF_ID (108544 + 1024)
#define MSG_SMEM2 (MOFF_ID + 512)

__device__ __forceinline__ void load_b32(uint32_t sb, int tid,
                                         const unsigned char* hs,
                                         const unsigned char* ls, int lines) {
    for (int i = tid; i < lines; i += MTHR) {
        cp_async16(sb + MOFF_B + i * 16, hs + i * 16);
        cp_async16(sb + MOFF_B + MB_SLICE + i * 16, ls + i * 16);
    }
    cp_commit();
}

// convert 64 fp32 values into hi/lo A tile at row r, col base cb
__device__ __forceinline__ void put64(char* smc, int r, int cb, const float v[64]) {
    #pragma unroll
    for (int b = 0; b < 4; ++b) {
        uint32_t hi[8], lo[8];
        #pragma unroll
        for (int q = 0; q < 8; ++q) {
            float a = v[b * 16 + q * 2], c = v[b * 16 + q * 2 + 1];
            __nv_bfloat16 h0 = __float2bfloat16(a), h1 = __float2bfloat16(c);
            hi[q] = pk(h0, h1);
            lo[q] = pk(__float2bfloat16(a - __bfloat162float(h0)),
                       __float2bfloat16(c - __bfloat162float(h1)));
        }
        uint4* dh = (uint4*)(smc + MOFF_AH + r * MA_STRIDE + (cb + b * 16) * 2);
        uint4* dl = (uint4*)(smc + MOFF_AL + r * MA_STRIDE + (cb + b * 16) * 2);
        dh[0] = make_uint4(hi[0], hi[1], hi[2], hi[3]);
        dh[1] = make_uint4(hi[4], hi[5], hi[6], hi[7]);
        dl[0] = make_uint4(lo[0], lo[1], lo[2], lo[3]);
        dl[1] = make_uint4(lo[4], lo[5], lo[6], lo[7]);
    }
}

__device__ __forceinline__ void gather64(char* smc, int r, int cb, const float* __restrict__ rowp) {
    float v[64];
    #pragma unroll
    for (int b = 0; b < 16; ++b) {
        float4 t = *(const float4*)(rowp + b * 4);
        v[b * 4 + 0] = t.x; v[b * 4 + 1] = t.y; v[b * 4 + 2] = t.z; v[b * 4 + 3] = t.w;
    }
    put64(smc, r, cb, v);
}

// one K=32 slice mma pass; warp tile 32 rows x NT*8 cols; accf[(mt*NT+nt)*4+q]
template<int NT>
__device__ __forceinline__ void mma_sliceT(uint32_t sb, int kbase,
                                           int wm, int wn, int lane, float* accf) {
    #pragma unroll
    for (int ks = 0; ks < 2; ++ks) {
        int kg = kbase + ks * 16;
        uint32_t ah[2][4], al[2][4];
        #pragma unroll
        for (int mt = 0; mt < 2; ++mt) {
            int row = wm * 32 + mt * 16 + (lane & 15);
            uint32_t addr = sb + MOFF_AH + row * MA_STRIDE + (kg + (lane >> 4) * 8) * 2;
            ldmx4(ah[mt], addr);
            ldmx4(al[mt], addr + (MOFF_AL - MOFF_AH));
        }
        #pragma unroll
        for (int ntp = 0; ntp < NT / 2; ++ntp) {
            int q = lane >> 3, rr = lane & 7;
            int n = wn * (NT * 8) + ntp * 16 + (q >> 1) * 8 + rr;
            uint32_t baddr = sb + MOFF_B + n * 80 + (ks * 16 + (q & 1) * 8) * 2;
            uint32_t bh[4], bl[4];
            ldmx4(bh, baddr);
            ldmx4(bl, baddr + MB_SLICE);
            #pragma unroll
            for (int mt = 0; mt < 2; ++mt) {
                float* d0 = accf + (mt * NT + ntp * 2) * 4;
                float* d1 = accf + (mt * NT + ntp * 2 + 1) * 4;
                mma_bf16(d0, ah[mt], bh[0], bh[1]);
                mma_bf16(d0, ah[mt], bl[0], bl[1]);
                mma_bf16(d0, al[mt], bh[0], bh[1]);
                mma_bf16(d1, ah[mt], bh[2], bh[3]);
                mma_bf16(d1, ah[mt], bl[2], bl[3]);
                mma_bf16(d1, al[mt], bh[2], bh[3]);
            }
        }
    }
}

// ================= pre kernel: P = x @ W1half per node =================
__global__ void __launch_bounds__(MTHR, 2)
pre_mma_kernel(const float* __restrict__ x1, const float* __restrict__ x2, int N) {
    int g = blockIdx.y >> 1, half = blockIdx.y & 1;
    const float* x = g ? x2 : x1;
    float* P = (half ? g_p2 : g_p1) + (size_t)g * N * HH;

    extern __shared__ char smc[];
    uint32_t sb = smem_u32(smc);

    int tid = threadIdx.x, wid = tid >> 5, lane = tid & 31;
    int base = blockIdx.x * 64;
    int wm = wid & 1, wn = wid >> 1;
    int gr = lane >> 2, gc = lane & 3;

    load_b32(sb, tid, g_wtile[0][half * 4][0], g_wtile[0][half * 4][1], 1280);
    if (tid < 128) {
        int r = tid >> 1, seg = tid & 1;
        int node = base + r; if (node >= N) node = N - 1;
        gather64(smc, r, seg * 64, x + (size_t)node * DD + seg * 64);
    }
    cp_wait<0>();
    __syncthreads();

    float accf[64];
    #pragma unroll
    for (int i = 0; i < 64; ++i) accf[i] = 0.f;

    for (int s = 0; s < 4; ++s) {
        mma_sliceT<8>(sb, s * 32, wm, wn, lane, accf);
        __syncthreads();
        if (s < 3) {
            load_b32(sb, tid, g_wtile[0][half * 4 + s + 1][0], g_wtile[0][half * 4 + s + 1][1], 1280);
            cp_wait<0>();
            __syncthreads();
        }
    }

    #pragma unroll
    for (int mt = 0; mt < 2; ++mt) {
        int r0 = wm * 32 + mt * 16 + gr;
        int r1 = r0 + 8;
        int n0 = base + r0, n1 = base + r1;
        #pragma unroll
        for (int nt = 0; nt < 8; ++nt) {
            int col = wn * 64 + nt * 8 + 2 * gc;
            float* a = accf + (mt * 8 + nt) * 4;
            if (n0 < N) *(float2*)(P + (size_t)n0 * HH + col) = make_float2(a[0], a[1]);
            if (n1 < N) *(float2*)(P + (size_t)n1 * HH + col) = make_float2(a[2], a[3]);
        }
    }
}

// ================= msg kernel: H = relu(P1[src]+P2[tgt]+b1); M = H@W2; scatter =================
__global__ void __launch_bounds__(MTHR, 2)
msg_mma_kernel(const int* __restrict__ ei1, const int* __restrict__ ei2,
               const float* __restrict__ b1, const float* __restrict__ b2,
               int N, int E) {
    int g = blockIdx.y;
    const int* ei = g ? ei2 : ei1;
    float* messages = g_messages + (size_t)g * N * HH;
    const float* P1 = g_p1 + (size_t)g * N * HH;
    const float* P2 = g_p2 + (size_t)g * N * HH;

    extern __shared__ char smc[];
    uint32_t sb = smem_u32(smc);
    float* b1s = (float*)(smc + MOFF_BIAS);
    int* s_src = (int*)(smc + MOFF_ID);
    int* s_tgt = s_src + 64;

    int tid = threadIdx.x, wid = tid >> 5, lane = tid & 31;
    int base = blockIdx.x * 64;

    b1s[tid] = b1[tid];
    if (tid < 64) {
        int e = base + tid;
        s_tgt[tid] = (e < E) ? ei[e] : 0;
        s_src[tid] = (e < E) ? ei[E + e] : 0;
    }
    __syncthreads();

    int wm = wid & 1, wn = wid >> 1;
    int gr = lane >> 2, gc = lane & 3;

    load_b32(sb, tid, g_wtile[1][0][0], g_wtile[1][0][1], 1280);
    {
        int r = tid >> 2, seg = tid & 3;
        const float* p1r = P1 + (size_t)s_src[r] * HH + seg * 64;
        const float* p2r = P2 + (size_t)s_tgt[r] * HH + seg * 64;
        const float* bb = b1s + seg * 64;
        float v[64];
        #pragma unroll
        for (int b = 0; b < 16; ++b) {
            float4 u = *(const float4*)(p1r + b * 4);
            float4 w = *(const float4*)(p2r + b * 4);
            float4 bv = *(const float4*)(bb + b * 4);
            v[b * 4 + 0] = fmaxf(u.x + w.x + bv.x, 0.f);
            v[b * 4 + 1] = fmaxf(u.y + w.y + bv.y, 0.f);
            v[b * 4 + 2] = fmaxf(u.z + w.z + bv.z, 0.f);
            v[b * 4 + 3] = fmaxf(u.w + w.w + bv.w, 0.f);
        }
        put64(smc, r, seg * 64, v);
    }
    cp_wait<0>();
    __syncthreads();

    float accf[64];
    #pragma unroll
    for (int i = 0; i < 64; ++i) accf[i] = 0.f;

    for (int s = 0; s < 8; ++s) {
        mma_sliceT<8>(sb, s * 32, wm, wn, lane, accf);
        __syncthreads();
        if (s < 7) {
            load_b32(sb, tid, g_wtile[1][s + 1][0], g_wtile[1][s + 1][1], 1280);
            cp_wait<0>();
            __syncthreads();
        }
    }

    #pragma unroll
    for (int mt = 0; mt < 2; ++mt) {
        int r0 = wm * 32 + mt * 16 + gr;
        int r1 = r0 + 8;
        bool v0 = (base + r0) < E, v1 = (base + r1) < E;
        float* m0 = messages + (size_t)s_tgt[r0] * HH;
        float* m1 = messages + (size_t)s_tgt[r1] * HH;
        #pragma unroll
        for (int nt = 0; nt < 8; ++nt) {
            int col = wn * 64 + nt * 8 + 2 * gc;
            float2 bv = *(const float2*)(b2 + col);
            float* a = accf + (mt * 8 + nt) * 4;
            if (v0) red_add_v2(m0 + col, a[0] + bv.x, a[1] + bv.y);
            if (v1) red_add_v2(m1 + col, a[2] + bv.x, a[3] + bv.y);
        }
    }
}

// ================= upd kernel (msg-style, 256 thr, occ 2) =================
__global__ void __launch_bounds__(MTHR, 2)
upd_mma_kernel(const float* __restrict__ x1, const float* __restrict__ x2,
               const float* __restrict__ b1u, const float* __restrict__ b2u,
               float* __restrict__ out, int N) {
    int g = blockIdx.y;
    const float* x = g ? x2 : x1;
    const float* messages = g_messages + (size_t)g * N * HH;
    const float* att = g_att + (size_t)g * N * DD;
    float* o = out + (size_t)g * N * DD;

    extern __shared__ char smc[];
    uint32_t sb = smem_u32(smc);
    float* b1s = (float*)(smc + MOFF_BIAS);

    int tid = threadIdx.x, wid = tid >> 5, lane = tid & 31;
    int base = blockIdx.x * 64;
    int wm = wid & 1, wn = wid >> 1;
    int gr = lane >> 2, gc = lane & 3;
    int r = tid >> 2, seg = tid & 3;
    int node = base + r;
    if (node >= N) node = N - 1;

    b1s[tid] = b1u[tid];

    // ---- phase A: A tile = messages[node] (cols 0..255 of u) ----
    load_b32(sb, tid, g_uw1s[0][0], g_uw1s[0][1], 1280);
    gather64(smc, r, seg * 64, messages + (size_t)node * HH + seg * 64);
    cp_wait<0>();
    __syncthreads();

    float accf[64];
    #pragma unroll
    for (int i = 0; i < 64; ++i) accf[i] = 0.f;

    for (int s = 0; s < 8; ++s) {
        mma_sliceT<8>(sb, s * 32, wm, wn, lane, accf);
        __syncthreads();
        if (s < 7) {
            load_b32(sb, tid, g_uw1s[s + 1][0], g_uw1s[s + 1][1], 1280);
            cp_wait<0>();
            __syncthreads();
        }
    }

    // ---- phase B: A tile = [att | x] (cols 256..511 of u) ----
    load_b32(sb, tid, g_uw1s[8][0], g_uw1s[8][1], 1280);
    {
        const float* src = (seg < 2) ? (att + (size_t)node * DD + seg * 64)
                                     : (x + (size_t)node * DD + (seg - 2) * 64);
        gather64(smc, r, seg * 64, src);
    }
    cp_wait<0>();
    __syncthreads();

    for (int s = 0; s < 8; ++s) {
        mma_sliceT<8>(sb, s * 32, wm, wn, lane, accf);
        __syncthreads();
        if (s < 7) {
            load_b32(sb, tid, g_uw1s[s + 9][0], g_uw1s[s + 9][1], 1280);
            cp_wait<0>();
            __syncthreads();
        }
    }

    // ---- epilogue 1: H = relu(D + b1u) -> A tile; load first W2u slice ----
    load_b32(sb, tid, g_uw2s[0][0], g_uw2s[0][1], 640);
    #pragma unroll
    for (int nt = 0; nt < 8; ++nt) {
        int col = wn * 64 + nt * 8 + 2 * gc;
        float2 bv = *(const float2*)(b1s + col);
        #pragma unroll
        for (int mt = 0; mt < 2; ++mt) {
            float* a = accf + (mt * 8 + nt) * 4;
            float f0 = fmaxf(a[0] + bv.x, 0.f);
            float f1 = fmaxf(a[1] + bv.y, 0.f);
            float f2 = fmaxf(a[2] + bv.x, 0.f);
            float f3 = fmaxf(a[3] + bv.y, 0.f);
            __nv_bfloat16 h0 = __float2bfloat16(f0), h1 = __float2bfloat16(f1);
            __nv_bfloat16 h2 = __float2bfloat16(f2), h3 = __float2bfloat16(f3);
            int r0 = wm * 32 + mt * 16 + gr;
            *(uint32_t*)(smc + MOFF_AH + r0 * MA_STRIDE + col * 2) = pk(h0, h1);
            *(uint32_t*)(smc + MOFF_AL + r0 * MA_STRIDE + col * 2) =
                pk(__float2bfloat16(f0 - __bfloat162float(h0)),
                   __float2bfloat16(f1 - __bfloat162float(h1)));
            *(uint32_t*)(smc + MOFF_AH + (r0 + 8) * MA_STRIDE + col * 2) = pk(h2, h3);
            *(uint32_t*)(smc + MOFF_AL + (r0 + 8) * MA_STRIDE + col * 2) =
                pk(__float2bfloat16(f2 - __bfloat162float(h2)),
                   __float2bfloat16(f3 - __bfloat162float(h3)));
            a[0] = a[1] = a[2] = a[3] = 0.f;
        }
    }
    cp_wait<0>();
    __syncthreads();

    // ---- layer 2: out = x + H @ W2u + b2u; warp tile 32 x 32 ----
    for (int s = 0; s < 8; ++s) {
        mma_sliceT<4>(sb, s * 32, wm, wn, lane, accf);
        __syncthreads();
        if (s < 7) {
            load_b32(sb, tid, g_uw2s[s + 1][0], g_uw2s[s + 1][1], 640);
            cp_wait<0>();
            __syncthreads();
        }
    }

    #pragma unroll
    for (int mt = 0; mt < 2; ++mt) {
        int r0 = wm * 32 + mt * 16 + gr;
        int r1 = r0 + 8;
        int n0 = base + r0, n1 = base + r1;
        #pragma unroll
        for (int nt = 0; nt < 4; ++nt) {
            int col = wn * 32 + nt * 8 + 2 * gc;
            float2 bv = *(const float2*)(b2u + col);
            float* a = accf + (mt * 4 + nt) * 4;
            if (n0 < N) {
                float2 xv = *(const float2*)(x + (size_t)n0 * DD + col);
                *(float2*)(o + (size_t)n0 * DD + col) =
                    make_float2(a[0] + bv.x + xv.x, a[1] + bv.y + xv.y);
            }
            if (n1 < N) {
                float2 xv = *(const float2*)(x + (size_t)n1 * DD + col);
                *(float2*)(o + (size_t)n1 * DD + col) =
                    make_float2(a[2] + bv.x + xv.x, a[3] + bv.y + xv.y);
            }
        }
    }
}

// ---------------- block-diagonal cross attention (round-13 version) ----------------
#define ATT_MAXC 320
#define ATT_S 129
#define ATT_SBOFF (ATT_MAXC * ATT_S)
#define ATT_RBOFF (ATT_SBOFF + 8 * ATT_MAXC)
#define ATT_SMEM ((ATT_RBOFF + 8 * 132) * 4)

__global__ void attn_kernel(const float* __restrict__ x1,
                            const float* __restrict__ x2, int N) {
    extern __shared__ float asm_[];
    float* colsm = asm_;
    int b = blockIdx.x;
    int dir = blockIdx.y;
    const float* rowsrc = dir ? x2 : x1;
    const float* colsrc = dir ? x1 : x2;
    float* att = g_att + (size_t)dir * N * DD;
    int rs = g_seg[(dir * NB + b) * 2 + 0];
    int re = g_seg[(dir * NB + b) * 2 + 1];
    int cs = g_seg[((1 - dir) * NB + b) * 2 + 0];
    int ce = g_seg[((1 - dir) * NB + b) * 2 + 1];
    const float* mean = g_colmeans + (1 - dir) * DD;
    int nc = ce - cs;

    int warp = threadIdx.x >> 5, lane = threadIdx.x & 31;
    float* sbuf = asm_ + ATT_SBOFF + warp * ATT_MAXC;
    float* rowb = asm_ + ATT_RBOFF + warp * 132;

    if (nc == 0) {
        for (int i = rs + warp; i < re; i += 8) {
            float4 a = *(const float4*)(rowsrc + (size_t)i * DD + lane * 4);
            float4 mv = *(const float4*)(mean + lane * 4);
            float4 res;
            res.x = a.x - mv.x; res.y = a.y - mv.y;
            res.z = a.z - mv.z; res.w = a.w - mv.w;
            *(float4*)(att + (size_t)i * DD + lane * 4) = res;
        }
        return;
    }

    if (nc <= ATT_MAXC) {
        for (int idx = threadIdx.x; idx < nc * DD; idx += 256) {
            int j = idx >> 7, k = idx & 127;
            colsm[j * ATT_S + k] = colsrc[(size_t)(cs + j) * DD + k];
        }
        __syncthreads();

        int npass = (nc + 31) >> 5;
        for (int i = rs + warp; i < re; i += 8) {
            float4 a4 = *(const float4*)(rowsrc + (size_t)i * DD + lane * 4);
            *(float4*)(rowb + lane * 4) = a4;
            __syncwarp();

            float m = -3.4e38f;
            for (int cb = 0; cb < npass; ++cb) {
                int j = cb * 32 + lane;
                float s = -3.4e38f;
                if (j < nc) {
                    s = 0.f;
                    const float* cp = colsm + j * ATT_S;
                    #pragma unroll 8
                    for (int k = 0; k < DD; ++k) s = fmaf(rowb[k], cp[k], s);
                    sbuf[j] = s;
                }
                m = fmaxf(m, s);
            }
            #pragma unroll
            for (int o = 16; o; o >>= 1) m = fmaxf(m, __shfl_xor_sync(0xffffffffu, m, o));

            float se = 0.f;
            for (int cb = 0; cb < npass; ++cb) {
                int j = cb * 32 + lane;
                if (j < nc) {
                    float w = __expf(sbuf[j] - m);
                    sbuf[j] = w;
                    se += w;
                }
            }
            #pragma unroll
            for (int o = 16; o; o >>= 1) se += __shfl_xor_sync(0xffffffffu, se, o);
            float inv = 1.f / se;
            __syncwarp();

            float acc0 = 0.f, acc1 = 0.f, acc2 = 0.f, acc3 = 0.f;
            for (int j = 0; j < nc; ++j) {
                float w = sbuf[j];
                const float* cp = colsm + j * ATT_S + lane;
                acc0 = fmaf(w, cp[0],  acc0);
                acc1 = fmaf(w, cp[32], acc1);
                acc2 = fmaf(w, cp[64], acc2);
                acc3 = fmaf(w, cp[96], acc3);
            }
            float* ar = att + (size_t)i * DD;
            ar[lane]      = rowb[lane]      - acc0 * inv;
            ar[lane + 32] = rowb[lane + 32] - acc1 * inv;
            ar[lane + 64] = rowb[lane + 64] - acc2 * inv;
            ar[lane + 96] = rowb[lane + 96] - acc3 * inv;
            __syncwarp();
        }
    } else {
        for (int i = rs + warp; i < re; i += 8) {
            float4 a = *(const float4*)(rowsrc + (size_t)i * DD + lane * 4);
            float m = -3.4e38f;
            for (int j = cs; j < ce; ++j) {
                float4 bv = *(const float4*)(colsrc + (size_t)j * DD + lane * 4);
                float d = a.x * bv.x + a.y * bv.y + a.z * bv.z + a.w * bv.w;
                #pragma unroll
                for (int o = 16; o; o >>= 1) d += __shfl_xor_sync(0xffffffffu, d, o);
                m = fmaxf(m, d);
            }
            float se = 0.f;
            float4 acc = make_float4(0.f, 0.f, 0.f, 0.f);
            for (int j = cs; j < ce; ++j) {
                float4 bv = *(const float4*)(colsrc + (size_t)j * DD + lane * 4);
                float d = a.x * bv.x + a.y * bv.y + a.z * bv.z + a.w * bv.w;
                #pragma unroll
                for (int o = 16; o; o >>= 1) d += __shfl_xor_sync(0xffffffffu, d, o);
                float w = __expf(d - m);
                se += w;
                acc.x = fmaf(w, bv.x, acc.x);
                acc.y = fmaf(w, bv.y, acc.y);
                acc.z = fmaf(w, bv.z, acc.z);
                acc.w = fmaf(w, bv.w, acc.w);
            }
            float inv = 1.f / se;
            float4 res;
            res.x = a.x - acc.x * inv; res.y = a.y - acc.y * inv;
            res.z = a.z - acc.z * inv; res.w = a.w - acc.w * inv;
            *(float4*)(att + (size_t)i * DD + lane * 4) = res;
        }
    }
}

// ---------------- launcher ----------------
extern "C" void kernel_launch(void* const* d_in, const int* in_sizes, int n_in,
                              void* d_out, int out_size) {
    const float* x1   = (const float*)d_in[0];
    const int*   ei1  = (const int*)d_in[1];
    const int*   bat1 = (const int*)d_in[2];
    const float* x2   = (const float*)d_in[3];
    const int*   ei2  = (const int*)d_in[4];
    const int*   bat2 = (const int*)d_in[5];
    const float* mW1 = (const float*)d_in[6];
    const float* mb1 = (const float*)d_in[7];
    const float* mW2 = (const float*)d_in[8];
    const float* mb2 = (const float*)d_in[9];
    const float* uW1 = (const float*)d_in[10];
    const float* ub1 = (const float*)d_in[11];
    const float* uW2 = (const float*)d_in[12];
    const float* ub2 = (const float*)d_in[13];
    float* out = (float*)d_out;

    int N = in_sizes[2];
    int E = in_sizes[1] / 2;

    cudaFuncSetAttribute(pre_mma_kernel, cudaFuncAttributeMaxDynamicSharedMemorySize, MSG_SMEM2);
    cudaFuncSetAttribute(msg_mma_kernel, cudaFuncAttributeMaxDynamicSharedMemorySize, MSG_SMEM2);
    cudaFuncSetAttribute(upd_mma_kernel, cudaFuncAttributeMaxDynamicSharedMemorySize, MSG_SMEM2);
    cudaFuncSetAttribute(attn_kernel, cudaFuncAttributeMaxDynamicSharedMemorySize, ATT_SMEM);

    int zn4 = 2 * N * HH / 4;
    zero_msgs_kernel<<<(zn4 + 255) / 256, 256>>>(zn4);
    seg_kernel<<<1, 128>>>(bat1, bat2, N);
    colmean_kernel<<<2, DD>>>(x1, x2, N);
    prep_all_kernel<<<1152, 256>>>(mW1, mW2, uW1, uW2);

    dim3 pgrid((N + 63) / 64, 4);
    pre_mma_kernel<<<pgrid, MTHR, MSG_SMEM2>>>(x1, x2, N);

    dim3 mgrid((E + 63) / 64, 2);
    msg_mma_kernel<<<mgrid, MTHR, MSG_SMEM2>>>(ei1, ei2, mb1, mb2, N, E);

    attn_kernel<<<dim3(NB, 2), 256, ATT_SMEM>>>(x1, x2, N);

    dim3 ugrid((N + 63) / 64, 2);
    upd_mma_kernel<<<ugrid, MTHR, MSG_SMEM2>>>(x1, x2, ub1, ub2, out, N);
}

// round 15
// speedup vs baseline: 1.0680x; 1.0680x over previous
#include <cuda_runtime.h>
#include <cuda_bf16.h>
#include <math.h>
#include <stdint.h>

// ---------------- problem constants ----------------
#define DD      128
#define HH      256
#define MAXN    8192
#define NB      64
#define NTHR    512
#define MTHR    256

// scratch
__device__ float g_messages[2ull * MAXN * HH];
__device__ float g_p1[2ull * MAXN * HH];       // x @ W1[0:128]   per node
__device__ float g_p2[2ull * MAXN * HH];       // x @ W1[128:256] per node
__device__ float g_att[2ull * MAXN * DD];
__device__ float g_colmeans[2 * DD];
__device__ int   g_seg[2 * NB * 2];

// msg weights: K=32 slices, row stride 80 B (32 data cols + 8 pad)
#define MB_SLICE 20480            // 256 n-rows * 80
__device__ __align__(16) unsigned char g_wtile[2][8][2][MB_SLICE];
// upd weights: K=64 slices, row stride 144 B
#define HCT_BYTES  36864
#define HCT2_BYTES 18432
__device__ __align__(16) unsigned char g_uw1[8][2][HCT_BYTES];
__device__ __align__(16) unsigned char g_uw2[4][2][HCT2_BYTES];

// ---------------- PTX helpers ----------------
__device__ __forceinline__ uint32_t smem_u32(const void* p) {
    uint32_t a;
    asm("{ .reg .u64 t; cvta.to.shared.u64 t, %1; cvt.u32.u64 %0, t; }" : "=r"(a) : "l"(p));
    return a;
}
__device__ __forceinline__ void cp_async16(unsigned int saddr, const void* gptr) {
    asm volatile("cp.async.cg.shared.global [%0], [%1], 16;" :: "r"(saddr), "l"(gptr));
}
__device__ __forceinline__ void cp_commit() { asm volatile("cp.async.commit_group;"); }
template<int N>
__device__ __forceinline__ void cp_wait() { asm volatile("cp.async.wait_group %0;" :: "n"(N)); }
__device__ __forceinline__ void red_add_v4(float* p, float a, float b, float c, float d) {
    asm volatile("red.global.add.v4.f32 [%0], {%1,%2,%3,%4};"
                 :: "l"(p), "f"(a), "f"(b), "f"(c), "f"(d) : "memory");
}
__device__ __forceinline__ void ldmx4(uint32_t r[4], uint32_t addr) {
    asm volatile("ldmatrix.sync.aligned.m8n8.x4.shared.b16 {%0,%1,%2,%3}, [%4];"
        : "=r"(r[0]), "=r"(r[1]), "=r"(r[2]), "=r"(r[3]) : "r"(addr));
}
__device__ __forceinline__ void mma_bf16(float d[4], const uint32_t a[4],
                                         uint32_t b0, uint32_t b1) {
    asm volatile("mma.sync.aligned.m16n8k16.row.col.f32.bf16.bf16.f32 "
        "{%0,%1,%2,%3}, {%4,%5,%6,%7}, {%8,%9}, {%0,%1,%2,%3};"
        : "+f"(d[0]), "+f"(d[1]), "+f"(d[2]), "+f"(d[3])
        : "r"(a[0]), "r"(a[1]), "r"(a[2]), "r"(a[3]), "r"(b0), "r"(b1));
}
__device__ __forceinline__ uint32_t pk(__nv_bfloat16 a, __nv_bfloat16 b) {
    __nv_bfloat162 t = __halves2bfloat162(a, b);
    return *reinterpret_cast<uint32_t*>(&t);
}

// ---------------- tiny setup kernels ----------------
__global__ void zero_msgs_kernel(int n4) {
    int i = blockIdx.x * blockDim.x + threadIdx.x;
    if (i < n4) ((float4*)g_messages)[i] = make_float4(0.f, 0.f, 0.f, 0.f);
}

__global__ void seg_kernel(const int* __restrict__ b1, const int* __restrict__ b2, int N) {
    int t = threadIdx.x;
    if (t >= 2 * NB) return;
    int g = t / NB, b = t % NB;
    const int* arr = g ? b2 : b1;
    int lo = 0, hi = N;
    while (lo < hi) { int m = (lo + hi) >> 1; if (arr[m] < b) lo = m + 1; else hi = m; }
    int start = lo;
    lo = 0; hi = N;
    while (lo < hi) { int m = (lo + hi) >> 1; if (arr[m] <= b) lo = m + 1; else hi = m; }
    g_seg[t * 2 + 0] = start;
    g_seg[t * 2 + 1] = lo;
}

__global__ void colmean_kernel(const float* __restrict__ x1, const float* __restrict__ x2, int N) {
    const float* x = blockIdx.x ? x2 : x1;
    int c = threadIdx.x;
    float s0 = 0.f, s1 = 0.f, s2 = 0.f, s3 = 0.f;
    int r = 0;
    for (; r + 3 < N; r += 4) {
        s0 += x[(size_t)(r + 0) * DD + c];
        s1 += x[(size_t)(r + 1) * DD + c];
        s2 += x[(size_t)(r + 2) * DD + c];
        s3 += x[(size_t)(r + 3) * DD + c];
    }
    for (; r < N; ++r) s0 += x[(size_t)r * DD + c];
    g_colmeans[blockIdx.x * DD + c] = (s0 + s1 + s2 + s3) * (1.f / (float)N);
}

__device__ __forceinline__ void split_store(unsigned char* hdst, unsigned char* ldst,
                                            size_t off, float w) {
    __nv_bfloat16 h = __float2bfloat16(w);
    __nv_bfloat16 l = __float2bfloat16(w - __bfloat162float(h));
    *(__nv_bfloat16*)(hdst + off) = h;
    *(__nv_bfloat16*)(ldst + off) = l;
}

__global__ void prep_all_kernel(const float* __restrict__ mW1, const float* __restrict__ mW2,
                                const float* __restrict__ uW1, const float* __restrict__ uW2) {
    int idx = blockIdx.x * 256 + threadIdx.x;
    if (idx < 131072) {
        int layer = idx >> 16;
        int e = idx & 65535;
        int k = e >> 8, n = e & 255;
        const float* W = layer ? mW2 : mW1;
        split_store(g_wtile[layer][k >> 5][0], g_wtile[layer][k >> 5][1],
                    (size_t)n * 80 + (size_t)(k & 31) * 2, W[e]);
    } else if (idx < 262144) {
        int e = idx - 131072;
        int k = e >> 8, n = e & 255;
        split_store(g_uw1[k >> 6][0], g_uw1[k >> 6][1],
                    (size_t)n * 144 + (size_t)(k & 63) * 2, uW1[e]);
    } else {
        int e = idx - 262144;
        int k = e >> 7, n = e & 127;
        split_store(g_uw2[k >> 6][0], g_uw2[k >> 6][1],
                    (size_t)n * 144 + (size_t)(k & 63) * 2, uW2[e]);
    }
}

// ================= shared msg-style mma pieces (256 thr, occ 2) =================
#define MA_STRIDE 528
#define MOFF_AH 0
#define MOFF_AL 33792
#define MOFF_B  67584
#define MOFF_BIAS 108544
#define MOFF_ID (108544 + 1024)
#define MSG_SMEM2 (MOFF_ID + 512)

__device__ __forceinline__ void load_msg_b(uint32_t sb, int tid, int layer, int s) {
    const unsigned char* hs = g_wtile[layer][s][0];
    const unsigned char* ls = g_wtile[layer][s][1];
    #pragma unroll
    for (int t = 0; t < 5; ++t) {
        int i = tid + t * MTHR;
        cp_async16(sb + MOFF_B + i * 16, hs + i * 16);
        cp_async16(sb + MOFF_B + MB_SLICE + i * 16, ls + i * 16);
    }
    cp_commit();
}

__device__ __forceinline__ void put64(char* smc, int r, int cb, const float v[64]) {
    #pragma unroll
    for (int b = 0; b < 4; ++b) {
        uint32_t hi[8], lo[8];
        #pragma unroll
        for (int q = 0; q < 8; ++q) {
            float a = v[b * 16 + q * 2], c = v[b * 16 + q * 2 + 1];
            __nv_bfloat16 h0 = __float2bfloat16(a), h1 = __float2bfloat16(c);
            hi[q] = pk(h0, h1);
            lo[q] = pk(__float2bfloat16(a - __bfloat162float(h0)),
                       __float2bfloat16(c - __bfloat162float(h1)));
        }
        uint4* dh = (uint4*)(smc + MOFF_AH + r * MA_STRIDE + (cb + b * 16) * 2);
        uint4* dl = (uint4*)(smc + MOFF_AL + r * MA_STRIDE + (cb + b * 16) * 2);
        dh[0] = make_uint4(hi[0], hi[1], hi[2], hi[3]);
        dh[1] = make_uint4(hi[4], hi[5], hi[6], hi[7]);
        dl[0] = make_uint4(lo[0], lo[1], lo[2], lo[3]);
        dl[1] = make_uint4(lo[4], lo[5], lo[6], lo[7]);
    }
}

__device__ __forceinline__ void gather64(char* smc, int r, int cb, const float* __restrict__ rowp) {
    float v[64];
    #pragma unroll
    for (int b = 0; b < 16; ++b) {
        float4 t = *(const float4*)(rowp + b * 4);
        v[b * 4 + 0] = t.x; v[b * 4 + 1] = t.y; v[b * 4 + 2] = t.z; v[b * 4 + 3] = t.w;
    }
    put64(smc, r, cb, v);
}

__device__ __forceinline__ void mma_slice(uint32_t sb, int kbase,
                                          int wm, int wn, int lane, float acc[2][8][4]) {
    #pragma unroll
    for (int ks = 0; ks < 2; ++ks) {
        int kg = kbase + ks * 16;
        uint32_t ah[2][4], al[2][4];
        #pragma unroll
        for (int mt = 0; mt < 2; ++mt) {
            int row = wm * 32 + mt * 16 + (lane & 15);
            uint32_t addr = sb + MOFF_AH + row * MA_STRIDE + (kg + (lane >> 4) * 8) * 2;
            ldmx4(ah[mt], addr);
            ldmx4(al[mt], addr + (MOFF_AL - MOFF_AH));
        }
        #pragma unroll
        for (int ntp = 0; ntp < 4; ++ntp) {
            int q = lane >> 3, rr = lane & 7;
            int n = wn * 64 + ntp * 16 + (q >> 1) * 8 + rr;
            uint32_t baddr = sb + MOFF_B + n * 80 + (ks * 16 + (q & 1) * 8) * 2;
            uint32_t bh[4], bl[4];
            ldmx4(bh, baddr);
            ldmx4(bl, baddr + MB_SLICE);
            #pragma unroll
            for (int mt = 0; mt < 2; ++mt) {
                mma_bf16(acc[mt][ntp * 2],     ah[mt], bh[0], bh[1]);
                mma_bf16(acc[mt][ntp * 2],     ah[mt], bl[0], bl[1]);
                mma_bf16(acc[mt][ntp * 2],     al[mt], bh[0], bh[1]);
                mma_bf16(acc[mt][ntp * 2 + 1], ah[mt], bh[2], bh[3]);
                mma_bf16(acc[mt][ntp * 2 + 1], ah[mt], bl[2], bl[3]);
                mma_bf16(acc[mt][ntp * 2 + 1], al[mt], bh[2], bh[3]);
            }
        }
    }
}

// ================= pre kernel: P = x @ W1half per node =================
__global__ void __launch_bounds__(MTHR, 2)
pre_mma_kernel(const float* __restrict__ x1, const float* __restrict__ x2, int N) {
    int g = blockIdx.y >> 1, half = blockIdx.y & 1;
    const float* x = g ? x2 : x1;
    float* P = (half ? g_p2 : g_p1) + (size_t)g * N * HH;

    extern __shared__ char smc[];
    uint32_t sb = smem_u32(smc);

    int tid = threadIdx.x, wid = tid >> 5, lane = tid & 31;
    int base = blockIdx.x * 64;
    int wm = wid & 1, wn = wid >> 1;
    int gr = lane >> 2, gc = lane & 3;

    load_msg_b(sb, tid, 0, half * 4);
    if (tid < 128) {
        int r = tid >> 1, seg = tid & 1;
        int node = base + r; if (node >= N) node = N - 1;
        gather64(smc, r, seg * 64, x + (size_t)node * DD + seg * 64);
    }
    cp_wait<0>();
    __syncthreads();

    float acc[2][8][4];
    #pragma unroll
    for (int mt = 0; mt < 2; ++mt)
        #pragma unroll
        for (int nt = 0; nt < 8; ++nt)
            #pragma unroll
            for (int q = 0; q < 4; ++q) acc[mt][nt][q] = 0.f;

    for (int s = 0; s < 4; ++s) {
        mma_slice(sb, s * 32, wm, wn, lane, acc);
        __syncthreads();
        if (s < 3) {
            load_msg_b(sb, tid, 0, half * 4 + s + 1);
            cp_wait<0>();
            __syncthreads();
        }
    }

    #pragma unroll
    for (int mt = 0; mt < 2; ++mt) {
        int r0 = wm * 32 + mt * 16 + gr;
        int r1 = r0 + 8;
        int n0 = base + r0, n1 = base + r1;
        #pragma unroll
        for (int nt = 0; nt < 8; ++nt) {
            int col = wn * 64 + nt * 8 + 2 * gc;
            if (n0 < N) *(float2*)(P + (size_t)n0 * HH + col) = make_float2(acc[mt][nt][0], acc[mt][nt][1]);
            if (n1 < N) *(float2*)(P + (size_t)n1 * HH + col) = make_float2(acc[mt][nt][2], acc[mt][nt][3]);
        }
    }
}

// ================= msg kernel: H = relu(P1[src]+P2[tgt]+b1); M = H@W2; scatter =================
__global__ void __launch_bounds__(MTHR, 2)
msg_mma_kernel(const int* __restrict__ ei1, const int* __restrict__ ei2,
               const float* __restrict__ b1, const float* __restrict__ b2,
               int N, int E) {
    int g = blockIdx.y;
    const int* ei = g ? ei2 : ei1;
    float* messages = g_messages + (size_t)g * N * HH;
    const float* P1 = g_p1 + (size_t)g * N * HH;
    const float* P2 = g_p2 + (size_t)g * N * HH;

    extern __shared__ char smc[];
    uint32_t sb = smem_u32(smc);
    float* b1s = (float*)(smc + MOFF_BIAS);
    int* s_src = (int*)(smc + MOFF_ID);
    int* s_tgt = s_src + 64;

    int tid = threadIdx.x, wid = tid >> 5, lane = tid & 31;
    int base = blockIdx.x * 64;

    b1s[tid] = b1[tid];
    if (tid < 64) {
        int e = base + tid;
        s_tgt[tid] = (e < E) ? ei[e] : 0;
        s_src[tid] = (e < E) ? ei[E + e] : 0;
    }
    __syncthreads();

    int wm = wid & 1, wn = wid >> 1;
    int gr = lane >> 2, gc = lane & 3;

    load_msg_b(sb, tid, 1, 0);
    {
        int r = tid >> 2, seg = tid & 3;
        const float* p1r = P1 + (size_t)s_src[r] * HH + seg * 64;
        const float* p2r = P2 + (size_t)s_tgt[r] * HH + seg * 64;
        const float* bb = b1s + seg * 64;
        float v[64];
        #pragma unroll
        for (int b = 0; b < 16; ++b) {
            float4 u = *(const float4*)(p1r + b * 4);
            float4 w = *(const float4*)(p2r + b * 4);
            float4 bv = *(const float4*)(bb + b * 4);
            v[b * 4 + 0] = fmaxf(u.x + w.x + bv.x, 0.f);
            v[b * 4 + 1] = fmaxf(u.y + w.y + bv.y, 0.f);
            v[b * 4 + 2] = fmaxf(u.z + w.z + bv.z, 0.f);
            v[b * 4 + 3] = fmaxf(u.w + w.w + bv.w, 0.f);
        }
        put64(smc, r, seg * 64, v);
    }
    cp_wait<0>();
    __syncthreads();

    float acc[2][8][4];
    #pragma unroll
    for (int mt = 0; mt < 2; ++mt)
        #pragma unroll
        for (int nt = 0; nt < 8; ++nt)
            #pragma unroll
            for (int q = 0; q < 4; ++q) acc[mt][nt][q] = 0.f;

    for (int s = 0; s < 8; ++s) {
        mma_slice(sb, s * 32, wm, wn, lane, acc);
        __syncthreads();
        if (s < 7) {
            load_msg_b(sb, tid, 1, s + 1);
            cp_wait<0>();
            __syncthreads();
        }
    }

    // scatter-add: lane-pair exchange -> one red.v4 per fragment instead of two red.v2
    #pragma unroll
    for (int mt = 0; mt < 2; ++mt) {
        int r0 = wm * 32 + mt * 16 + gr;
        int r1 = r0 + 8;
        bool v0 = (base + r0) < E, v1 = (base + r1) < E;
        float* m0 = messages + (size_t)s_tgt[r0] * HH;
        float* m1 = messages + (size_t)s_tgt[r1] * HH;
        #pragma unroll
        for (int nt = 0; nt < 8; ++nt) {
            int col = wn * 64 + nt * 8 + 2 * gc;
            float2 bv = *(const float2*)(b2 + col);
            float s0 = acc[mt][nt][0] + bv.x;
            float s1 = acc[mt][nt][1] + bv.y;
            float s2 = acc[mt][nt][2] + bv.x;
            float s3 = acc[mt][nt][3] + bv.y;
            float p0 = __shfl_xor_sync(0xffffffffu, s0, 1);
            float p1 = __shfl_xor_sync(0xffffffffu, s1, 1);
            float p2 = __shfl_xor_sync(0xffffffffu, s2, 1);
            float p3 = __shfl_xor_sync(0xffffffffu, s3, 1);
            int colbase = wn * 64 + nt * 8 + (gc >> 1) * 4;
            if ((gc & 1) == 0) {
                if (v0) red_add_v4(m0 + colbase, s0, s1, p0, p1);
            } else {
                if (v1) red_add_v4(m1 + colbase, p2, p3, s2, s3);
            }
        }
    }
}

// ================= upd kernel (round-13 proven 512-thr version) =================
#define OFF_AH 0
#define OFF_AL 17408
#define OFF_B  34816
#define BBUF_BYTES 73728
#define OFF_ID (34816 + 2*BBUF_BYTES)
#define UPD_SMEM (OFF_ID + 1024)

__device__ __forceinline__ void gather_a(char* smc, int r, int seg, const float* __restrict__ rowp) {
    const float4* row = (const float4*)(rowp + seg * 16);
    uint32_t hi[8], lo[8];
    #pragma unroll
    for (int q = 0; q < 4; ++q) {
        float4 v = row[q];
        __nv_bfloat16 h0 = __float2bfloat16(v.x), h1 = __float2bfloat16(v.y);
        __nv_bfloat16 h2 = __float2bfloat16(v.z), h3 = __float2bfloat16(v.w);
        hi[q * 2 + 0] = pk(h0, h1);
        hi[q * 2 + 1] = pk(h2, h3);
        lo[q * 2 + 0] = pk(__float2bfloat16(v.x - __bfloat162float(h0)),
                           __float2bfloat16(v.y - __bfloat162float(h1)));
        lo[q * 2 + 1] = pk(__float2bfloat16(v.z - __bfloat162float(h2)),
                           __float2bfloat16(v.w - __bfloat162float(h3)));
    }
    uint4* dh = (uint4*)(smc + OFF_AH + r * 272 + seg * 32);
    uint4* dl = (uint4*)(smc + OFF_AL + r * 272 + seg * 32);
    dh[0] = make_uint4(hi[0], hi[1], hi[2], hi[3]);
    dh[1] = make_uint4(hi[4], hi[5], hi[6], hi[7]);
    dl[0] = make_uint4(lo[0], lo[1], lo[2], lo[3]);
    dl[1] = make_uint4(lo[4], lo[5], lo[6], lo[7]);
}

template<int NT>
__device__ __forceinline__ void mma_hc(uint32_t sb, int a_k0, uint32_t b_base,
                                       int wm, int wn, int lane, float acc[2][NT][4]) {
    #pragma unroll
    for (int ks = 0; ks < 4; ++ks) {
        int k0 = ks * 16;
        uint32_t ah[2][4], al[2][4];
        #pragma unroll
        for (int mt = 0; mt < 2; ++mt) {
            int row = wm * 32 + mt * 16 + (lane & 15);
            uint32_t addr = sb + OFF_AH + row * 272 + (a_k0 + k0 + (lane >> 4) * 8) * 2;
            ldmx4(ah[mt], addr);
            ldmx4(al[mt], addr + (OFF_AL - OFF_AH));
        }
        uint32_t bh[(NT + 1) / 2][4], bl[(NT + 1) / 2][4];
        #pragma unroll
        for (int ntp = 0; ntp < (NT + 1) / 2; ++ntp) {
            int q = lane >> 3, rr = lane & 7;
            int n = wn * (NT * 8) + ntp * 16 + (q >> 1) * 8 + rr;
            int kk = k0 + (q & 1) * 8;
            uint32_t addr = b_base + n * 144 + kk * 2;
            ldmx4(bh[ntp], addr);
            ldmx4(bl[ntp], addr + HCT_BYTES);
        }
        #pragma unroll
        for (int mt = 0; mt < 2; ++mt)
            #pragma unroll
            for (int nt = 0; nt < NT; ++nt) {
                int p = nt >> 1, h2 = (nt & 1) * 2;
                mma_bf16(acc[mt][nt], ah[mt], bh[p][h2], bh[p][h2 + 1]);
                mma_bf16(acc[mt][nt], ah[mt], bl[p][h2], bl[p][h2 + 1]);
                mma_bf16(acc[mt][nt], al[mt], bh[p][h2], bh[p][h2 + 1]);
            }
    }
}

__device__ __forceinline__ void load_b_hc(uint32_t b_base, int tid,
                                          const unsigned char* hsrc,
                                          const unsigned char* lsrc, int lines) {
    for (int t = tid; t < lines; t += NTHR) {
        cp_async16(b_base + t * 16, hsrc + t * 16);
        cp_async16(b_base + HCT_BYTES + t * 16, lsrc + t * 16);
    }
    cp_commit();
}

__global__ void __launch_bounds__(NTHR, 1)
upd_mma_kernel(const float* __restrict__ x1, const float* __restrict__ x2,
               const float* __restrict__ b1u, const float* __restrict__ b2u,
               float* __restrict__ out, int N) {
    int g = blockIdx.y;
    const float* x = g ? x2 : x1;
    const float* messages = g_messages + (size_t)g * N * HH;
    const float* att = g_att + (size_t)g * N * DD;
    float* o = out + (size_t)g * N * DD;

    extern __shared__ char smc[];
    uint32_t sb = smem_u32(smc);

    int tid = threadIdx.x, wid = tid >> 5, lane = tid & 31;
    int base = blockIdx.x * 64;
    int wm = wid & 1, wn = wid >> 1;
    int gr = lane >> 2, gc = lane & 3;
    int r = tid >> 3, seg = tid & 7;
    uint32_t bbuf[2] = { sb + OFF_B, sb + OFF_B + BBUF_BYTES };

    int node = base + r;
    if (node >= N) node = N - 1;
    const float* srcs[4] = {
        messages + (size_t)node * HH,
        messages + (size_t)node * HH + 128,
        att + (size_t)node * DD,
        x + (size_t)node * DD
    };

    float acc[2][4][4];
    #pragma unroll
    for (int mt = 0; mt < 2; ++mt)
        #pragma unroll
        for (int nt = 0; nt < 4; ++nt)
            #pragma unroll
            for (int q = 0; q < 4; ++q) acc[mt][nt][q] = 0.f;

    load_b_hc(bbuf[0], tid, g_uw1[0][0], g_uw1[0][1], 2304);
    gather_a(smc, r, seg, srcs[0]);
    load_b_hc(bbuf[1], tid, g_uw1[1][0], g_uw1[1][1], 2304);
    cp_wait<1>();
    __syncthreads();

    #pragma unroll
    for (int hc = 0; hc < 8; ++hc) {
        mma_hc<4>(sb, (hc & 1) * 64, bbuf[hc & 1], wm, wn, lane, acc);
        __syncthreads();
        if ((hc & 1) == 1 && hc < 7) gather_a(smc, r, seg, srcs[(hc + 1) >> 1]);
        if (hc + 2 < 8) {
            load_b_hc(bbuf[hc & 1], tid, g_uw1[hc + 2][0], g_uw1[hc + 2][1], 2304);
            cp_wait<1>();
        } else if (hc + 1 < 8) {
            cp_wait<0>();
        }
        __syncthreads();
    }

    uint32_t hh[2][4][2], hl[2][4][2];
    #pragma unroll
    for (int nt = 0; nt < 4; ++nt) {
        int col = wn * 32 + nt * 8 + 2 * gc;
        float2 bv = *(const float2*)(b1u + col);
        #pragma unroll
        for (int mt = 0; mt < 2; ++mt) {
            float f0 = fmaxf(acc[mt][nt][0] + bv.x, 0.f);
            float f1 = fmaxf(acc[mt][nt][1] + bv.y, 0.f);
            float f2 = fmaxf(acc[mt][nt][2] + bv.x, 0.f);
            float f3 = fmaxf(acc[mt][nt][3] + bv.y, 0.f);
            __nv_bfloat16 h0 = __float2bfloat16(f0), h1 = __float2bfloat16(f1);
            __nv_bfloat16 h2 = __float2bfloat16(f2), h3 = __float2bfloat16(f3);
            hh[mt][nt][0] = pk(h0, h1);
            hh[mt][nt][1] = pk(h2, h3);
            hl[mt][nt][0] = pk(__float2bfloat16(f0 - __bfloat162float(h0)),
                               __float2bfloat16(f1 - __bfloat162float(h1)));
            hl[mt][nt][1] = pk(__float2bfloat16(f2 - __bfloat162float(h2)),
                               __float2bfloat16(f3 - __bfloat162float(h3)));
            acc[mt][nt][0] = acc[mt][nt][1] = acc[mt][nt][2] = acc[mt][nt][3] = 0.f;
        }
    }

    int wm2 = wid & 1, wn2 = wid >> 1;
    float (*acc2)[2][4] = (float (*)[2][4])acc;

    load_b_hc(bbuf[0], tid, g_uw2[0][0], g_uw2[0][1], 1152);
    if (wn < 4) {
        #pragma unroll
        for (int mt = 0; mt < 2; ++mt) {
            int rr = wm * 32 + mt * 16 + gr;
            #pragma unroll
            for (int nt = 0; nt < 4; ++nt) {
                int cc = wn * 32 + nt * 8 + 2 * gc;
                *(uint32_t*)(smc + OFF_AH + rr * 272 + cc * 2)       = hh[mt][nt][0];
                *(uint32_t*)(smc + OFF_AL + rr * 272 + cc * 2)       = hl[mt][nt][0];
                *(uint32_t*)(smc + OFF_AH + (rr + 8) * 272 + cc * 2) = hh[mt][nt][1];
                *(uint32_t*)(smc + OFF_AL + (rr + 8) * 272 + cc * 2) = hl[mt][nt][1];
            }
        }
    }
    load_b_hc(bbuf[1], tid, g_uw2[1][0], g_uw2[1][1], 1152);
    cp_wait<1>();
    __syncthreads();

    #pragma unroll
    for (int hc = 0; hc < 4; ++hc) {
        mma_hc<2>(sb, (hc & 1) * 64, bbuf[hc & 1], wm2, wn2, lane, acc2);
        __syncthreads();
        if (hc == 1 && wn >= 4) {
            #pragma unroll
            for (int mt = 0; mt < 2; ++mt) {
                int rr = wm * 32 + mt * 16 + gr;
                #pragma unroll
                for (int nt = 0; nt < 4; ++nt) {
                    int cc = (wn & 3) * 32 + nt * 8 + 2 * gc;
                    *(uint32_t*)(smc + OFF_AH + rr * 272 + cc * 2)       = hh[mt][nt][0];
                    *(uint32_t*)(smc + OFF_AL + rr * 272 + cc * 2)       = hl[mt][nt][0];
                    *(uint32_t*)(smc + OFF_AH + (rr + 8) * 272 + cc * 2) = hh[mt][nt][1];
                    *(uint32_t*)(smc + OFF_AL + (rr + 8) * 272 + cc * 2) = hl[mt][nt][1];
                }
            }
        }
        if (hc + 2 < 4) {
            load_b_hc(bbuf[hc & 1], tid, g_uw2[hc + 2][0], g_uw2[hc + 2][1], 1152);
            cp_wait<1>();
        } else if (hc + 1 < 4) {
            cp_wait<0>();
        }
        __syncthreads();
    }

    #pragma unroll
    for (int mt = 0; mt < 2; ++mt) {
        int r0 = wm2 * 32 + mt * 16 + gr;
        int r1 = r0 + 8;
        int n0 = base + r0, n1 = base + r1;
        #pragma unroll
        for (int nt = 0; nt < 2; ++nt) {
            int col = wn2 * 16 + nt * 8 + 2 * gc;
            float2 bv = *(const float2*)(b2u + col);
            if (n0 < N) {
                float2 xv = *(const float2*)(x + (size_t)n0 * DD + col);
                float2 rr;
                rr.x = acc2[mt][nt][0] + bv.x + xv.x;
                rr.y = acc2[mt][nt][1] + bv.y + xv.y;
                *(float2*)(o + (size_t)n0 * DD + col) = rr;
            }
            if (n1 < N) {
                float2 xv = *(const float2*)(x + (size_t)n1 * DD + col);
                float2 rr;
                rr.x = acc2[mt][nt][2] + bv.x + xv.x;
                rr.y = acc2[mt][nt][3] + bv.y + xv.y;
                *(float2*)(o + (size_t)n1 * DD + col) = rr;
            }
        }
    }
}

// ---------------- block-diagonal cross attention (smem col staging) ----------------
#define ATT_MAXC 320
#define ATT_S 129
#define ATT_SBOFF (ATT_MAXC * ATT_S)
#define ATT_RBOFF (ATT_SBOFF + 8 * ATT_MAXC)
#define ATT_SMEM ((ATT_RBOFF + 8 * 132) * 4)

__global__ void attn_kernel(const float* __restrict__ x1,
                            const float* __restrict__ x2, int N) {
    extern __shared__ float asm_[];
    float* colsm = asm_;
    int b = blockIdx.x;
    int dir = blockIdx.y;
    const float* rowsrc = dir ? x2 : x1;
    const float* colsrc = dir ? x1 : x2;
    float* att = g_att + (size_t)dir * N * DD;
    int rs = g_seg[(dir * NB + b) * 2 + 0];
    int re = g_seg[(dir * NB + b) * 2 + 1];
    int cs = g_seg[((1 - dir) * NB + b) * 2 + 0];
    int ce = g_seg[((1 - dir) * NB + b) * 2 + 1];
    const float* mean = g_colmeans + (1 - dir) * DD;
    int nc = ce - cs;

    int warp = threadIdx.x >> 5, lane = threadIdx.x & 31;
    float* sbuf = asm_ + ATT_SBOFF + warp * ATT_MAXC;
    float* rowb = asm_ + ATT_RBOFF + warp * 132;

    if (nc == 0) {
        for (int i = rs + warp; i < re; i += 8) {
            float4 a = *(const float4*)(rowsrc + (size_t)i * DD + lane * 4);
            float4 mv = *(const float4*)(mean + lane * 4);
            float4 res;
            res.x = a.x - mv.x; res.y = a.y - mv.y;
            res.z = a.z - mv.z; res.w = a.w - mv.w;
            *(float4*)(att + (size_t)i * DD + lane * 4) = res;
        }
        return;
    }

    if (nc <= ATT_MAXC) {
        for (int idx = threadIdx.x; idx < nc * DD; idx += 256) {
            int j = idx >> 7, k = idx & 127;
            colsm[j * ATT_S + k] = colsrc[(size_t)(cs + j) * DD + k];
        }
        __syncthreads();

        int npass = (nc + 31) >> 5;
        for (int i = rs + warp; i < re; i += 8) {
            float4 a4 = *(const float4*)(rowsrc + (size_t)i * DD + lane * 4);
            *(float4*)(rowb + lane * 4) = a4;
            __syncwarp();

            float m = -3.4e38f;
            for (int cb = 0; cb < npass; ++cb) {
                int j = cb * 32 + lane;
                float s = -3.4e38f;
                if (j < nc) {
                    s = 0.f;
                    const float* cp = colsm + j * ATT_S;
                    #pragma unroll 8
                    for (int k = 0; k < DD; ++k) s = fmaf(rowb[k], cp[k], s);
                    sbuf[j] = s;
                }
                m = fmaxf(m, s);
            }
            #pragma unroll
            for (int o = 16; o; o >>= 1) m = fmaxf(m, __shfl_xor_sync(0xffffffffu, m, o));

            float se = 0.f;
            for (int cb = 0; cb < npass; ++cb) {
                int j = cb * 32 + lane;
                if (j < nc) {
                    float w = __expf(sbuf[j] - m);
                    sbuf[j] = w;
                    se += w;
                }
            }
            #pragma unroll
            for (int o = 16; o; o >>= 1) se += __shfl_xor_sync(0xffffffffu, se, o);
            float inv = 1.f / se;
            __syncwarp();

            float acc0 = 0.f, acc1 = 0.f, acc2 = 0.f, acc3 = 0.f;
            for (int j = 0; j < nc; ++j) {
                float w = sbuf[j];
                const float* cp = colsm + j * ATT_S + lane;
                acc0 = fmaf(w, cp[0],  acc0);
                acc1 = fmaf(w, cp[32], acc1);
                acc2 = fmaf(w, cp[64], acc2);
                acc3 = fmaf(w, cp[96], acc3);
            }
            float* ar = att + (size_t)i * DD;
            ar[lane]      = rowb[lane]      - acc0 * inv;
            ar[lane + 32] = rowb[lane + 32] - acc1 * inv;
            ar[lane + 64] = rowb[lane + 64] - acc2 * inv;
            ar[lane + 96] = rowb[lane + 96] - acc3 * inv;
            __syncwarp();
        }
    } else {
        for (int i = rs + warp; i < re; i += 8) {
            float4 a = *(const float4*)(rowsrc + (size_t)i * DD + lane * 4);
            float m = -3.4e38f;
            for (int j = cs; j < ce; ++j) {
                float4 bv = *(const float4*)(colsrc + (size_t)j * DD + lane * 4);
                float d = a.x * bv.x + a.y * bv.y + a.z * bv.z + a.w * bv.w;
                #pragma unroll
                for (int o = 16; o; o >>= 1) d += __shfl_xor_sync(0xffffffffu, d, o);
                m = fmaxf(m, d);
            }
            float se = 0.f;
            float4 acc = make_float4(0.f, 0.f, 0.f, 0.f);
            for (int j = cs; j < ce; ++j) {
                float4 bv = *(const float4*)(colsrc + (size_t)j * DD + lane * 4);
                float d = a.x * bv.x + a.y * bv.y + a.z * bv.z + a.w * bv.w;
                #pragma unroll
                for (int o = 16; o; o >>= 1) d += __shfl_xor_sync(0xffffffffu, d, o);
                float w = __expf(d - m);
                se += w;
                acc.x = fmaf(w, bv.x, acc.x);
                acc.y = fmaf(w, bv.y, acc.y);
                acc.z = fmaf(w, bv.z, acc.z);
                acc.w = fmaf(w, bv.w, acc.w);
            }
            float inv = 1.f / se;
            float4 res;
            res.x = a.x - acc.x * inv; res.y = a.y - acc.y * inv;
            res.z = a.z - acc.z * inv; res.w = a.w - acc.w * inv;
            *(float4*)(att + (size_t)i * DD + lane * 4) = res;
        }
    }
}

// ---------------- launcher ----------------
extern "C" void kernel_launch(void* const* d_in, const int* in_sizes, int n_in,
                              void* d_out, int out_size) {
    const float* x1   = (const float*)d_in[0];
    const int*   ei1  = (const int*)d_in[1];
    const int*   bat1 = (const int*)d_in[2];
    const float* x2   = (const float*)d_in[3];
    const int*   ei2  = (const int*)d_in[4];
    const int*   bat2 = (const int*)d_in[5];
    const float* mW1 = (const float*)d_in[6];
    const float* mb1 = (const float*)d_in[7];
    const float* mW2 = (const float*)d_in[8];
    const float* mb2 = (const float*)d_in[9];
    const float* uW1 = (const float*)d_in[10];
    const float* ub1 = (const float*)d_in[11];
    const float* uW2 = (const float*)d_in[12];
    const float* ub2 = (const float*)d_in[13];
    float* out = (float*)d_out;

    int N = in_sizes[2];
    int E = in_sizes[1] / 2;

    cudaFuncSetAttribute(pre_mma_kernel, cudaFuncAttributeMaxDynamicSharedMemorySize, MSG_SMEM2);
    cudaFuncSetAttribute(msg_mma_kernel, cudaFuncAttributeMaxDynamicSharedMemorySize, MSG_SMEM2);
    cudaFuncSetAttribute(upd_mma_kernel, cudaFuncAttributeMaxDynamicSharedMemorySize, UPD_SMEM);
    cudaFuncSetAttribute(attn_kernel, cudaFuncAttributeMaxDynamicSharedMemorySize, ATT_SMEM);

    int zn4 = 2 * N * HH / 4;
    zero_msgs_kernel<<<(zn4 + 255) / 256, 256>>>(zn4);
    seg_kernel<<<1, 128>>>(bat1, bat2, N);
    colmean_kernel<<<2, DD>>>(x1, x2, N);
    prep_all_kernel<<<1152, 256>>>(mW1, mW2, uW1, uW2);

    dim3 pgrid((N + 63) / 64, 4);
    pre_mma_kernel<<<pgrid, MTHR, MSG_SMEM2>>>(x1, x2, N);

    dim3 mgrid((E + 63) / 64, 2);
    msg_mma_kernel<<<mgrid, MTHR, MSG_SMEM2>>>(ei1, ei2, mb1, mb2, N, E);

    attn_kernel<<<dim3(NB, 2), 256, ATT_SMEM>>>(x1, x2, N);

    dim3 ugrid((N + 63) / 64, 2);
    upd_mma_kernel<<<ugrid, NTHR, UPD_SMEM>>>(x1, x2, ub1, ub2, out, N);
}

// round 16
// speedup vs baseline: 1.3443x; 1.2587x over previous
#include <cuda_runtime.h>
#include <cuda_fp16.h>
#include <math.h>
#include <stdint.h>

// ---------------- problem constants ----------------
#define DD      128
#define HH      256
#define MAXN    8192
#define NB      64
#define NTHR    512
#define MTHR    256

// scratch
__device__ float g_messages[2ull * MAXN * HH];
__device__ float g_p1[2ull * MAXN * HH];       // x @ W1[0:128]   per node
__device__ float g_p2[2ull * MAXN * HH];       // x @ W1[128:256] per node
__device__ float g_att[2ull * MAXN * DD];
__device__ float g_colmeans[2 * DD];
__device__ int   g_seg[2 * NB * 2];

// fp16 weight tiles
// msg/pre: K=32 slices, row stride 80 B (32 fp16 data cols + 8 pad)
#define MB_SLICE 20480            // 256 n-rows * 80
__device__ __align__(16) unsigned char g_wtile[2][8][MB_SLICE];
// upd: K=64 slices, row stride 144 B
#define HCT_BYTES  36864          // 256 rows * 144
#define HCT2_BYTES 18432          // 128 rows * 144
__device__ __align__(16) unsigned char g_uw1[8][HCT_BYTES];
__device__ __align__(16) unsigned char g_uw2[4][HCT2_BYTES];

// ---------------- PTX helpers ----------------
__device__ __forceinline__ uint32_t smem_u32(const void* p) {
    uint32_t a;
    asm("{ .reg .u64 t; cvta.to.shared.u64 t, %1; cvt.u32.u64 %0, t; }" : "=r"(a) : "l"(p));
    return a;
}
__device__ __forceinline__ void cp_async16(unsigned int saddr, const void* gptr) {
    asm volatile("cp.async.cg.shared.global [%0], [%1], 16;" :: "r"(saddr), "l"(gptr));
}
__device__ __forceinline__ void cp_commit() { asm volatile("cp.async.commit_group;"); }
template<int N>
__device__ __forceinline__ void cp_wait() { asm volatile("cp.async.wait_group %0;" :: "n"(N)); }
__device__ __forceinline__ void red_add_v2(float* p, float a, float b) {
    asm volatile("red.global.add.v2.f32 [%0], {%1,%2};" :: "l"(p), "f"(a), "f"(b) : "memory");
}
__device__ __forceinline__ void ldmx4(uint32_t r[4], uint32_t addr) {
    asm volatile("ldmatrix.sync.aligned.m8n8.x4.shared.b16 {%0,%1,%2,%3}, [%4];"
        : "=r"(r[0]), "=r"(r[1]), "=r"(r[2]), "=r"(r[3]) : "r"(addr));
}
__device__ __forceinline__ void mma_f16(float d[4], const uint32_t a[4],
                                        uint32_t b0, uint32_t b1) {
    asm volatile("mma.sync.aligned.m16n8k16.row.col.f32.f16.f16.f32 "
        "{%0,%1,%2,%3}, {%4,%5,%6,%7}, {%8,%9}, {%0,%1,%2,%3};"
        : "+f"(d[0]), "+f"(d[1]), "+f"(d[2]), "+f"(d[3])
        : "r"(a[0]), "r"(a[1]), "r"(a[2]), "r"(a[3]), "r"(b0), "r"(b1));
}
__device__ __forceinline__ uint32_t pk16(float a, float b) {
    __half2 t = __floats2half2_rn(a, b);
    return *reinterpret_cast<uint32_t*>(&t);
}

// ---------------- tiny setup kernels ----------------
__global__ void zero_msgs_kernel(int n4) {
    int i = blockIdx.x * blockDim.x + threadIdx.x;
    if (i < n4) ((float4*)g_messages)[i] = make_float4(0.f, 0.f, 0.f, 0.f);
}

__global__ void seg_kernel(const int* __restrict__ b1, const int* __restrict__ b2, int N) {
    int t = threadIdx.x;
    if (t >= 2 * NB) return;
    int g = t / NB, b = t % NB;
    const int* arr = g ? b2 : b1;
    int lo = 0, hi = N;
    while (lo < hi) { int m = (lo + hi) >> 1; if (arr[m] < b) lo = m + 1; else hi = m; }
    int start = lo;
    lo = 0; hi = N;
    while (lo < hi) { int m = (lo + hi) >> 1; if (arr[m] <= b) lo = m + 1; else hi = m; }
    g_seg[t * 2 + 0] = start;
    g_seg[t * 2 + 1] = lo;
}

__global__ void colmean_kernel(const float* __restrict__ x1, const float* __restrict__ x2, int N) {
    const float* x = blockIdx.x ? x2 : x1;
    int c = threadIdx.x;
    float s0 = 0.f, s1 = 0.f, s2 = 0.f, s3 = 0.f;
    int r = 0;
    for (; r + 3 < N; r += 4) {
        s0 += x[(size_t)(r + 0) * DD + c];
        s1 += x[(size_t)(r + 1) * DD + c];
        s2 += x[(size_t)(r + 2) * DD + c];
        s3 += x[(size_t)(r + 3) * DD + c];
    }
    for (; r < N; ++r) s0 += x[(size_t)r * DD + c];
    g_colmeans[blockIdx.x * DD + c] = (s0 + s1 + s2 + s3) * (1.f / (float)N);
}

__global__ void prep_all_kernel(const float* __restrict__ mW1, const float* __restrict__ mW2,
                                const float* __restrict__ uW1, const float* __restrict__ uW2) {
    int idx = blockIdx.x * 256 + threadIdx.x;
    if (idx < 131072) {
        int layer = idx >> 16;
        int e = idx & 65535;
        int k = e >> 8, n = e & 255;
        const float* W = layer ? mW2 : mW1;
        *(__half*)(g_wtile[layer][k >> 5] + (size_t)n * 80 + (size_t)(k & 31) * 2) =
            __float2half_rn(W[e]);
    } else if (idx < 262144) {
        int e = idx - 131072;
        int k = e >> 8, n = e & 255;
        *(__half*)(g_uw1[k >> 6] + (size_t)n * 144 + (size_t)(k & 63) * 2) =
            __float2half_rn(uW1[e]);
    } else {
        int e = idx - 262144;
        int k = e >> 7, n = e & 127;
        *(__half*)(g_uw2[k >> 6] + (size_t)n * 144 + (size_t)(k & 63) * 2) =
            __float2half_rn(uW2[e]);
    }
}

// ================= shared msg-style mma pieces (256 thr) =================
#define MA_STRIDE 528
#define MOFF_A 0
#define MOFF_B 33792
#define MOFF_BIAS 54272
#define MOFF_ID 55296
#define MSG_SMEM2 55808

__device__ __forceinline__ void load_msg_b(uint32_t sb, int tid, int layer, int s) {
    const unsigned char* hs = g_wtile[layer][s];
    #pragma unroll
    for (int t = 0; t < 5; ++t) {
        int i = tid + t * MTHR;
        cp_async16(sb + MOFF_B + i * 16, hs + i * 16);
    }
    cp_commit();
}

// convert 64 fp32 values into fp16 A tile at row r, col base cb
__device__ __forceinline__ void put64(char* smc, int r, int cb, const float v[64]) {
    #pragma unroll
    for (int b = 0; b < 8; ++b) {
        uint32_t h[4];
        #pragma unroll
        for (int q = 0; q < 4; ++q)
            h[q] = pk16(v[b * 8 + q * 2], v[b * 8 + q * 2 + 1]);
        *(uint4*)(smc + MOFF_A + r * MA_STRIDE + (cb + b * 8) * 2) =
            make_uint4(h[0], h[1], h[2], h[3]);
    }
}

__device__ __forceinline__ void gather64(char* smc, int r, int cb, const float* __restrict__ rowp) {
    float v[64];
    #pragma unroll
    for (int b = 0; b < 16; ++b) {
        float4 t = *(const float4*)(rowp + b * 4);
        v[b * 4 + 0] = t.x; v[b * 4 + 1] = t.y; v[b * 4 + 2] = t.z; v[b * 4 + 3] = t.w;
    }
    put64(smc, r, cb, v);
}

// one K=32 slice mma pass; warp tile 32 rows x 64 cols; single-term fp16
__device__ __forceinline__ void mma_slice(uint32_t sb, int kbase,
                                          int wm, int wn, int lane, float acc[2][8][4]) {
    #pragma unroll
    for (int ks = 0; ks < 2; ++ks) {
        int kg = kbase + ks * 16;
        uint32_t ah[2][4];
        #pragma unroll
        for (int mt = 0; mt < 2; ++mt) {
            int row = wm * 32 + mt * 16 + (lane & 15);
            ldmx4(ah[mt], sb + MOFF_A + row * MA_STRIDE + (kg + (lane >> 4) * 8) * 2);
        }
        #pragma unroll
        for (int ntp = 0; ntp < 4; ++ntp) {
            int q = lane >> 3, rr = lane & 7;
            int n = wn * 64 + ntp * 16 + (q >> 1) * 8 + rr;
            uint32_t bh[4];
            ldmx4(bh, sb + MOFF_B + n * 80 + (ks * 16 + (q & 1) * 8) * 2);
            #pragma unroll
            for (int mt = 0; mt < 2; ++mt) {
                mma_f16(acc[mt][ntp * 2],     ah[mt], bh[0], bh[1]);
                mma_f16(acc[mt][ntp * 2 + 1], ah[mt], bh[2], bh[3]);
            }
        }
    }
}

// ================= pre kernel: P = x @ W1half per node =================
__global__ void __launch_bounds__(MTHR, 2)
pre_mma_kernel(const float* __restrict__ x1, const float* __restrict__ x2, int N) {
    int g = blockIdx.y >> 1, half = blockIdx.y & 1;
    const float* x = g ? x2 : x1;
    float* P = (half ? g_p2 : g_p1) + (size_t)g * N * HH;

    extern __shared__ char smc[];
    uint32_t sb = smem_u32(smc);

    int tid = threadIdx.x, wid = tid >> 5, lane = tid & 31;
    int base = blockIdx.x * 64;
    int wm = wid & 1, wn = wid >> 1;
    int gr = lane >> 2, gc = lane & 3;

    load_msg_b(sb, tid, 0, half * 4);
    if (tid < 128) {
        int r = tid >> 1, seg = tid & 1;
        int node = base + r; if (node >= N) node = N - 1;
        gather64(smc, r, seg * 64, x + (size_t)node * DD + seg * 64);
    }
    cp_wait<0>();
    __syncthreads();

    float acc[2][8][4];
    #pragma unroll
    for (int mt = 0; mt < 2; ++mt)
        #pragma unroll
        for (int nt = 0; nt < 8; ++nt)
            #pragma unroll
            for (int q = 0; q < 4; ++q) acc[mt][nt][q] = 0.f;

    for (int s = 0; s < 4; ++s) {
        mma_slice(sb, s * 32, wm, wn, lane, acc);
        __syncthreads();
        if (s < 3) {
            load_msg_b(sb, tid, 0, half * 4 + s + 1);
            cp_wait<0>();
            __syncthreads();
        }
    }

    #pragma unroll
    for (int mt = 0; mt < 2; ++mt) {
        int r0 = wm * 32 + mt * 16 + gr;
        int r1 = r0 + 8;
        int n0 = base + r0, n1 = base + r1;
        #pragma unroll
        for (int nt = 0; nt < 8; ++nt) {
            int col = wn * 64 + nt * 8 + 2 * gc;
            if (n0 < N) *(float2*)(P + (size_t)n0 * HH + col) = make_float2(acc[mt][nt][0], acc[mt][nt][1]);
            if (n1 < N) *(float2*)(P + (size_t)n1 * HH + col) = make_float2(acc[mt][nt][2], acc[mt][nt][3]);
        }
    }
}

// ================= msg kernel: H = relu(P1[src]+P2[tgt]+b1); M = H@W2; scatter =================
__global__ void __launch_bounds__(MTHR, 2)
msg_mma_kernel(const int* __restrict__ ei1, const int* __restrict__ ei2,
               const float* __restrict__ b1, const float* __restrict__ b2,
               int N, int E) {
    int g = blockIdx.y;
    const int* ei = g ? ei2 : ei1;
    float* messages = g_messages + (size_t)g * N * HH;
    const float* P1 = g_p1 + (size_t)g * N * HH;
    const float* P2 = g_p2 + (size_t)g * N * HH;

    extern __shared__ char smc[];
    uint32_t sb = smem_u32(smc);
    float* b1s = (float*)(smc + MOFF_BIAS);
    int* s_src = (int*)(smc + MOFF_ID);
    int* s_tgt = s_src + 64;

    int tid = threadIdx.x, wid = tid >> 5, lane = tid & 31;
    int base = blockIdx.x * 64;

    b1s[tid] = b1[tid];
    if (tid < 64) {
        int e = base + tid;
        s_tgt[tid] = (e < E) ? ei[e] : 0;
        s_src[tid] = (e < E) ? ei[E + e] : 0;
    }
    __syncthreads();

    int wm = wid & 1, wn = wid >> 1;
    int gr = lane >> 2, gc = lane & 3;

    load_msg_b(sb, tid, 1, 0);
    {
        int r = tid >> 2, seg = tid & 3;
        const float* p1r = P1 + (size_t)s_src[r] * HH + seg * 64;
        const float* p2r = P2 + (size_t)s_tgt[r] * HH + seg * 64;
        const float* bb = b1s + seg * 64;
        float v[64];
        #pragma unroll
        for (int b = 0; b < 16; ++b) {
            float4 u = *(const float4*)(p1r + b * 4);
            float4 w = *(const float4*)(p2r + b * 4);
            float4 bv = *(const float4*)(bb + b * 4);
            v[b * 4 + 0] = fmaxf(u.x + w.x + bv.x, 0.f);
            v[b * 4 + 1] = fmaxf(u.y + w.y + bv.y, 0.f);
            v[b * 4 + 2] = fmaxf(u.z + w.z + bv.z, 0.f);
            v[b * 4 + 3] = fmaxf(u.w + w.w + bv.w, 0.f);
        }
        put64(smc, r, seg * 64, v);
    }
    cp_wait<0>();
    __syncthreads();

    float acc[2][8][4];
    #pragma unroll
    for (int mt = 0; mt < 2; ++mt)
        #pragma unroll
        for (int nt = 0; nt < 8; ++nt)
            #pragma unroll
            for (int q = 0; q < 4; ++q) acc[mt][nt][q] = 0.f;

    for (int s = 0; s < 8; ++s) {
        mma_slice(sb, s * 32, wm, wn, lane, acc);
        __syncthreads();
        if (s < 7) {
            load_msg_b(sb, tid, 1, s + 1);
            cp_wait<0>();
            __syncthreads();
        }
    }

    #pragma unroll
    for (int mt = 0; mt < 2; ++mt) {
        int r0 = wm * 32 + mt * 16 + gr;
        int r1 = r0 + 8;
        bool v0 = (base + r0) < E, v1 = (base + r1) < E;
        float* m0 = messages + (size_t)s_tgt[r0] * HH;
        float* m1 = messages + (size_t)s_tgt[r1] * HH;
        #pragma unroll
        for (int nt = 0; nt < 8; ++nt) {
            int col = wn * 64 + nt * 8 + 2 * gc;
            float2 bv = *(const float2*)(b2 + col);
            if (v0) red_add_v2(m0 + col, acc[mt][nt][0] + bv.x, acc[mt][nt][1] + bv.y);
            if (v1) red_add_v2(m1 + col, acc[mt][nt][2] + bv.x, acc[mt][nt][3] + bv.y);
        }
    }
}

// ================= upd kernel (512 thr, now occ 2 via fp16) =================
#define OFF_A 0
#define OFF_B 17408
#define BBUF_BYTES 36864
#define UPD_SMEM (17408 + 2*36864)   // 91136

__device__ __forceinline__ void gather_a(char* smc, int r, int seg, const float* __restrict__ rowp) {
    const float4* row = (const float4*)(rowp + seg * 16);
    uint32_t h[8];
    #pragma unroll
    for (int q = 0; q < 4; ++q) {
        float4 v = row[q];
        h[q * 2 + 0] = pk16(v.x, v.y);
        h[q * 2 + 1] = pk16(v.z, v.w);
    }
    uint4* d = (uint4*)(smc + OFF_A + r * 272 + seg * 32);
    d[0] = make_uint4(h[0], h[1], h[2], h[3]);
    d[1] = make_uint4(h[4], h[5], h[6], h[7]);
}

template<int NT>
__device__ __forceinline__ void mma_hc(uint32_t sb, int a_k0, uint32_t b_base,
                                       int wm, int wn, int lane, float acc[2][NT][4]) {
    #pragma unroll
    for (int ks = 0; ks < 4; ++ks) {
        int k0 = ks * 16;
        uint32_t ah[2][4];
        #pragma unroll
        for (int mt = 0; mt < 2; ++mt) {
            int row = wm * 32 + mt * 16 + (lane & 15);
            ldmx4(ah[mt], sb + OFF_A + row * 272 + (a_k0 + k0 + (lane >> 4) * 8) * 2);
        }
        uint32_t bh[(NT + 1) / 2][4];
        #pragma unroll
        for (int ntp = 0; ntp < (NT + 1) / 2; ++ntp) {
            int q = lane >> 3, rr = lane & 7;
            int n = wn * (NT * 8) + ntp * 16 + (q >> 1) * 8 + rr;
            int kk = k0 + (q & 1) * 8;
            ldmx4(bh[ntp], b_base + n * 144 + kk * 2);
        }
        #pragma unroll
        for (int mt = 0; mt < 2; ++mt)
            #pragma unroll
            for (int nt = 0; nt < NT; ++nt) {
                int p = nt >> 1, h2 = (nt & 1) * 2;
                mma_f16(acc[mt][nt], ah[mt], bh[p][h2], bh[p][h2 + 1]);
            }
    }
}

__device__ __forceinline__ void load_b_hc(uint32_t b_base, int tid,
                                          const unsigned char* hsrc, int lines) {
    for (int t = tid; t < lines; t += NTHR)
        cp_async16(b_base + t * 16, hsrc + t * 16);
    cp_commit();
}

__global__ void __launch_bounds__(NTHR, 2)
upd_mma_kernel(const float* __restrict__ x1, const float* __restrict__ x2,
               const float* __restrict__ b1u, const float* __restrict__ b2u,
               float* __restrict__ out, int N) {
    int g = blockIdx.y;
    const float* x = g ? x2 : x1;
    const float* messages = g_messages + (size_t)g * N * HH;
    const float* att = g_att + (size_t)g * N * DD;
    float* o = out + (size_t)g * N * DD;

    extern __shared__ char smc[];
    uint32_t sb = smem_u32(smc);

    int tid = threadIdx.x, wid = tid >> 5, lane = tid & 31;
    int base = blockIdx.x * 64;
    int wm = wid & 1, wn = wid >> 1;
    int gr = lane >> 2, gc = lane & 3;
    int r = tid >> 3, seg = tid & 7;
    uint32_t bbuf[2] = { sb + OFF_B, sb + OFF_B + BBUF_BYTES };

    int node = base + r;
    if (node >= N) node = N - 1;
    const float* srcs[4] = {
        messages + (size_t)node * HH,
        messages + (size_t)node * HH + 128,
        att + (size_t)node * DD,
        x + (size_t)node * DD
    };

    float acc[2][4][4];
    #pragma unroll
    for (int mt = 0; mt < 2; ++mt)
        #pragma unroll
        for (int nt = 0; nt < 4; ++nt)
            #pragma unroll
            for (int q = 0; q < 4; ++q) acc[mt][nt][q] = 0.f;

    load_b_hc(bbuf[0], tid, g_uw1[0], 2304);
    gather_a(smc, r, seg, srcs[0]);
    load_b_hc(bbuf[1], tid, g_uw1[1], 2304);
    cp_wait<1>();
    __syncthreads();

    #pragma unroll
    for (int hc = 0; hc < 8; ++hc) {
        mma_hc<4>(sb, (hc & 1) * 64, bbuf[hc & 1], wm, wn, lane, acc);
        __syncthreads();
        if ((hc & 1) == 1 && hc < 7) gather_a(smc, r, seg, srcs[(hc + 1) >> 1]);
        if (hc + 2 < 8) {
            load_b_hc(bbuf[hc & 1], tid, g_uw1[hc + 2], 2304);
            cp_wait<1>();
        } else if (hc + 1 < 8) {
            cp_wait<0>();
        }
        __syncthreads();
    }

    uint32_t hh[2][4][2];
    #pragma unroll
    for (int nt = 0; nt < 4; ++nt) {
        int col = wn * 32 + nt * 8 + 2 * gc;
        float2 bv = *(const float2*)(b1u + col);
        #pragma unroll
        for (int mt = 0; mt < 2; ++mt) {
            float f0 = fmaxf(acc[mt][nt][0] + bv.x, 0.f);
            float f1 = fmaxf(acc[mt][nt][1] + bv.y, 0.f);
            float f2 = fmaxf(acc[mt][nt][2] + bv.x, 0.f);
            float f3 = fmaxf(acc[mt][nt][3] + bv.y, 0.f);
            hh[mt][nt][0] = pk16(f0, f1);
            hh[mt][nt][1] = pk16(f2, f3);
            acc[mt][nt][0] = acc[mt][nt][1] = acc[mt][nt][2] = acc[mt][nt][3] = 0.f;
        }
    }

    int wm2 = wid & 1, wn2 = wid >> 1;
    float (*acc2)[2][4] = (float (*)[2][4])acc;

    load_b_hc(bbuf[0], tid, g_uw2[0], 1152);
    if (wn < 4) {
        #pragma unroll
        for (int mt = 0; mt < 2; ++mt) {
            int rr = wm * 32 + mt * 16 + gr;
            #pragma unroll
            for (int nt = 0; nt < 4; ++nt) {
                int cc = wn * 32 + nt * 8 + 2 * gc;
                *(uint32_t*)(smc + OFF_A + rr * 272 + cc * 2)       = hh[mt][nt][0];
                *(uint32_t*)(smc + OFF_A + (rr + 8) * 272 + cc * 2) = hh[mt][nt][1];
            }
        }
    }
    load_b_hc(bbuf[1], tid, g_uw2[1], 1152);
    cp_wait<1>();
    __syncthreads();

    #pragma unroll
    for (int hc = 0; hc < 4; ++hc) {
        mma_hc<2>(sb, (hc & 1) * 64, bbuf[hc & 1], wm2, wn2, lane, acc2);
        __syncthreads();
        if (hc == 1 && wn >= 4) {
            #pragma unroll
            for (int mt = 0; mt < 2; ++mt) {
                int rr = wm * 32 + mt * 16 + gr;
                #pragma unroll
                for (int nt = 0; nt < 4; ++nt) {
                    int cc = (wn & 3) * 32 + nt * 8 + 2 * gc;
                    *(uint32_t*)(smc + OFF_A + rr * 272 + cc * 2)       = hh[mt][nt][0];
                    *(uint32_t*)(smc + OFF_A + (rr + 8) * 272 + cc * 2) = hh[mt][nt][1];
                }
            }
        }
        if (hc + 2 < 4) {
            load_b_hc(bbuf[hc & 1], tid, g_uw2[hc + 2], 1152);
            cp_wait<1>();
        } else if (hc + 1 < 4) {
            cp_wait<0>();
        }
        __syncthreads();
    }

    #pragma unroll
    for (int mt = 0; mt < 2; ++mt) {
        int r0 = wm2 * 32 + mt * 16 + gr;
        int r1 = r0 + 8;
        int n0 = base + r0, n1 = base + r1;
        #pragma unroll
        for (int nt = 0; nt < 2; ++nt) {
            int col = wn2 * 16 + nt * 8 + 2 * gc;
            float2 bv = *(const float2*)(b2u + col);
            if (n0 < N) {
                float2 xv = *(const float2*)(x + (size_t)n0 * DD + col);
                float2 rr;
                rr.x = acc2[mt][nt][0] + bv.x + xv.x;
                rr.y = acc2[mt][nt][1] + bv.y + xv.y;
                *(float2*)(o + (size_t)n0 * DD + col) = rr;
            }
            if (n1 < N) {
                float2 xv = *(const float2*)(x + (size_t)n1 * DD + col);
                float2 rr;
                rr.x = acc2[mt][nt][2] + bv.x + xv.x;
                rr.y = acc2[mt][nt][3] + bv.y + xv.y;
                *(float2*)(o + (size_t)n1 * DD + col) = rr;
            }
        }
    }
}

// ---------------- block-diagonal cross attention (round-13 proven) ----------------
#define ATT_MAXC 320
#define ATT_S 129
#define ATT_SBOFF (ATT_MAXC * ATT_S)
#define ATT_RBOFF (ATT_SBOFF + 8 * ATT_MAXC)
#define ATT_SMEM ((ATT_RBOFF + 8 * 132) * 4)

__global__ void attn_kernel(const float* __restrict__ x1,
                            const float* __restrict__ x2, int N) {
    extern __shared__ float asm_[];
    float* colsm = asm_;
    int b = blockIdx.x;
    int dir = blockIdx.y;
    const float* rowsrc = dir ? x2 : x1;
    const float* colsrc = dir ? x1 : x2;
    float* att = g_att + (size_t)dir * N * DD;
    int rs = g_seg[(dir * NB + b) * 2 + 0];
    int re = g_seg[(dir * NB + b) * 2 + 1];
    int cs = g_seg[((1 - dir) * NB + b) * 2 + 0];
    int ce = g_seg[((1 - dir) * NB + b) * 2 + 1];
    const float* mean = g_colmeans + (1 - dir) * DD;
    int nc = ce - cs;

    int warp = threadIdx.x >> 5, lane = threadIdx.x & 31;
    float* sbuf = asm_ + ATT_SBOFF + warp * ATT_MAXC;
    float* rowb = asm_ + ATT_RBOFF + warp * 132;

    if (nc == 0) {
        for (int i = rs + warp; i < re; i += 8) {
            float4 a = *(const float4*)(rowsrc + (size_t)i * DD + lane * 4);
            float4 mv = *(const float4*)(mean + lane * 4);
            float4 res;
            res.x = a.x - mv.x; res.y = a.y - mv.y;
            res.z = a.z - mv.z; res.w = a.w - mv.w;
            *(float4*)(att + (size_t)i * DD + lane * 4) = res;
        }
        return;
    }

    if (nc <= ATT_MAXC) {
        for (int idx = threadIdx.x; idx < nc * DD; idx += 256) {
            int j = idx >> 7, k = idx & 127;
            colsm[j * ATT_S + k] = colsrc[(size_t)(cs + j) * DD + k];
        }
        __syncthreads();

        int npass = (nc + 31) >> 5;
        for (int i = rs + warp; i < re; i += 8) {
            float4 a4 = *(const float4*)(rowsrc + (size_t)i * DD + lane * 4);
            *(float4*)(rowb + lane * 4) = a4;
            __syncwarp();

            float m = -3.4e38f;
            for (int cb = 0; cb < npass; ++cb) {
                int j = cb * 32 + lane;
                float s = -3.4e38f;
                if (j < nc) {
                    s = 0.f;
                    const float* cp = colsm + j * ATT_S;
                    #pragma unroll 8
                    for (int k = 0; k < DD; ++k) s = fmaf(rowb[k], cp[k], s);
                    sbuf[j] = s;
                }
                m = fmaxf(m, s);
            }
            #pragma unroll
            for (int o = 16; o; o >>= 1) m = fmaxf(m, __shfl_xor_sync(0xffffffffu, m, o));

            float se = 0.f;
            for (int cb = 0; cb < npass; ++cb) {
                int j = cb * 32 + lane;
                if (j < nc) {
                    float w = __expf(sbuf[j] - m);
                    sbuf[j] = w;
                    se += w;
                }
            }
            #pragma unroll
            for (int o = 16; o; o >>= 1) se += __shfl_xor_sync(0xffffffffu, se, o);
            float inv = 1.f / se;
            __syncwarp();

            float acc0 = 0.f, acc1 = 0.f, acc2 = 0.f, acc3 = 0.f;
            for (int j = 0; j < nc; ++j) {
                float w = sbuf[j];
                const float* cp = colsm + j * ATT_S + lane;
                acc0 = fmaf(w, cp[0],  acc0);
                acc1 = fmaf(w, cp[32], acc1);
                acc2 = fmaf(w, cp[64], acc2);
                acc3 = fmaf(w, cp[96], acc3);
            }
            float* ar = att + (size_t)i * DD;
            ar[lane]      = rowb[lane]      - acc0 * inv;
            ar[lane + 32] = rowb[lane + 32] - acc1 * inv;
            ar[lane + 64] = rowb[lane + 64] - acc2 * inv;
            ar[lane + 96] = rowb[lane + 96] - acc3 * inv;
            __syncwarp();
        }
    } else {
        for (int i = rs + warp; i < re; i += 8) {
            float4 a = *(const float4*)(rowsrc + (size_t)i * DD + lane * 4);
            float m = -3.4e38f;
            for (int j = cs; j < ce; ++j) {
                float4 bv = *(const float4*)(colsrc + (size_t)j * DD + lane * 4);
                float d = a.x * bv.x + a.y * bv.y + a.z * bv.z + a.w * bv.w;
                #pragma unroll
                for (int o = 16; o; o >>= 1) d += __shfl_xor_sync(0xffffffffu, d, o);
                m = fmaxf(m, d);
            }
            float se = 0.f;
            float4 acc = make_float4(0.f, 0.f, 0.f, 0.f);
            for (int j = cs; j < ce; ++j) {
                float4 bv = *(const float4*)(colsrc + (size_t)j * DD + lane * 4);
                float d = a.x * bv.x + a.y * bv.y + a.z * bv.z + a.w * bv.w;
                #pragma unroll
                for (int o = 16; o; o >>= 1) d += __shfl_xor_sync(0xffffffffu, d, o);
                float w = __expf(d - m);
                se += w;
                acc.x = fmaf(w, bv.x, acc.x);
                acc.y = fmaf(w, bv.y, acc.y);
                acc.z = fmaf(w, bv.z, acc.z);
                acc.w = fmaf(w, bv.w, acc.w);
            }
            float inv = 1.f / se;
            float4 res;
            res.x = a.x - acc.x * inv; res.y = a.y - acc.y * inv;
            res.z = a.z - acc.z * inv; res.w = a.w - acc.w * inv;
            *(float4*)(att + (size_t)i * DD + lane * 4) = res;
        }
    }
}

// ---------------- launcher ----------------
extern "C" void kernel_launch(void* const* d_in, const int* in_sizes, int n_in,
                              void* d_out, int out_size) {
    const float* x1   = (const float*)d_in[0];
    const int*   ei1  = (const int*)d_in[1];
    const int*   bat1 = (const int*)d_in[2];
    const float* x2   = (const float*)d_in[3];
    const int*   ei2  = (const int*)d_in[4];
    const int*   bat2 = (const int*)d_in[5];
    const float* mW1 = (const float*)d_in[6];
    const float* mb1 = (const float*)d_in[7];
    const float* mW2 = (const float*)d_in[8];
    const float* mb2 = (const float*)d_in[9];
    const float* uW1 = (const float*)d_in[10];
    const float* ub1 = (const float*)d_in[11];
    const float* uW2 = (const float*)d_in[12];
    const float* ub2 = (const float*)d_in[13];
    float* out = (float*)d_out;

    int N = in_sizes[2];
    int E = in_sizes[1] / 2;

    cudaFuncSetAttribute(pre_mma_kernel, cudaFuncAttributeMaxDynamicSharedMemorySize, MSG_SMEM2);
    cudaFuncSetAttribute(msg_mma_kernel, cudaFuncAttributeMaxDynamicSharedMemorySize, MSG_SMEM2);
    cudaFuncSetAttribute(upd_mma_kernel, cudaFuncAttributeMaxDynamicSharedMemorySize, UPD_SMEM);
    cudaFuncSetAttribute(attn_kernel, cudaFuncAttributeMaxDynamicSharedMemorySize, ATT_SMEM);

    int zn4 = 2 * N * HH / 4;
    zero_msgs_kernel<<<(zn4 + 255) / 256, 256>>>(zn4);
    seg_kernel<<<1, 128>>>(bat1, bat2, N);
    colmean_kernel<<<2, DD>>>(x1, x2, N);
    prep_all_kernel<<<1152, 256>>>(mW1, mW2, uW1, uW2);

    dim3 pgrid((N + 63) / 64, 4);
    pre_mma_kernel<<<pgrid, MTHR, MSG_SMEM2>>>(x1, x2, N);

    dim3 mgrid((E + 63) / 64, 2);
    msg_mma_kernel<<<mgrid, MTHR, MSG_SMEM2>>>(ei1, ei2, mb1, mb2, N, E);

    attn_kernel<<<dim3(NB, 2), 256, ATT_SMEM>>>(x1, x2, N);

    dim3 ugrid((N + 63) / 64, 2);
    upd_mma_kernel<<<ugrid, NTHR, UPD_SMEM>>>(x1, x2, ub1, ub2, out, N);
}

// round 17
// speedup vs baseline: 1.4022x; 1.0431x over previous
#include <cuda_runtime.h>
#include <cuda_fp16.h>
#include <math.h>
#include <stdint.h>

// ---------------- problem constants ----------------
#define DD      128
#define HH      256
#define MAXN    8192
#define NB      64
#define NTHR    512
#define MTHR    256

// scratch
__device__ float g_messages[2ull * MAXN * HH];
__device__ float g_p1[2ull * MAXN * HH];       // x @ W1[0:128]   per node
__device__ float g_p2[2ull * MAXN * HH];       // x @ W1[128:256] per node
__device__ float g_att[2ull * MAXN * DD];
__device__ float g_colmeans[2 * DD];
__device__ int   g_seg[2 * NB * 2];

// fp16 weight tiles
// msg/pre: K=32 slices, row stride 80 B (32 fp16 data cols + 8 pad)
#define MB_SLICE 20480            // 256 n-rows * 80
__device__ __align__(16) unsigned char g_wtile[2][8][MB_SLICE];
// upd: K=64 slices, row stride 144 B
#define HCT_BYTES  36864          // 256 rows * 144
#define HCT2_BYTES 18432          // 128 rows * 144
__device__ __align__(16) unsigned char g_uw1[8][HCT_BYTES];
__device__ __align__(16) unsigned char g_uw2[4][HCT2_BYTES];

// ---------------- PTX helpers ----------------
__device__ __forceinline__ uint32_t smem_u32(const void* p) {
    uint32_t a;
    asm("{ .reg .u64 t; cvta.to.shared.u64 t, %1; cvt.u32.u64 %0, t; }" : "=r"(a) : "l"(p));
    return a;
}
__device__ __forceinline__ void cp_async16(unsigned int saddr, const void* gptr) {
    asm volatile("cp.async.cg.shared.global [%0], [%1], 16;" :: "r"(saddr), "l"(gptr));
}
__device__ __forceinline__ void cp_commit() { asm volatile("cp.async.commit_group;"); }
template<int N>
__device__ __forceinline__ void cp_wait() { asm volatile("cp.async.wait_group %0;" :: "n"(N)); }
__device__ __forceinline__ void red_add_v2(float* p, float a, float b) {
    asm volatile("red.global.add.v2.f32 [%0], {%1,%2};" :: "l"(p), "f"(a), "f"(b) : "memory");
}
__device__ __forceinline__ void ldmx4(uint32_t r[4], uint32_t addr) {
    asm volatile("ldmatrix.sync.aligned.m8n8.x4.shared.b16 {%0,%1,%2,%3}, [%4];"
        : "=r"(r[0]), "=r"(r[1]), "=r"(r[2]), "=r"(r[3]) : "r"(addr));
}
__device__ __forceinline__ void mma_f16(float d[4], const uint32_t a[4],
                                        uint32_t b0, uint32_t b1) {
    asm volatile("mma.sync.aligned.m16n8k16.row.col.f32.f16.f16.f32 "
        "{%0,%1,%2,%3}, {%4,%5,%6,%7}, {%8,%9}, {%0,%1,%2,%3};"
        : "+f"(d[0]), "+f"(d[1]), "+f"(d[2]), "+f"(d[3])
        : "r"(a[0]), "r"(a[1]), "r"(a[2]), "r"(a[3]), "r"(b0), "r"(b1));
}
__device__ __forceinline__ uint32_t pk16(float a, float b) {
    __half2 t = __floats2half2_rn(a, b);
    return *reinterpret_cast<uint32_t*>(&t);
}

// ---------------- tiny setup kernels ----------------
__global__ void zero_msgs_kernel(int n4) {
    int i = blockIdx.x * blockDim.x + threadIdx.x;
    if (i < n4) ((float4*)g_messages)[i] = make_float4(0.f, 0.f, 0.f, 0.f);
}

__global__ void seg_kernel(const int* __restrict__ b1, const int* __restrict__ b2, int N) {
    int t = threadIdx.x;
    if (t >= 2 * NB) return;
    int g = t / NB, b = t % NB;
    const int* arr = g ? b2 : b1;
    int lo = 0, hi = N;
    while (lo < hi) { int m = (lo + hi) >> 1; if (arr[m] < b) lo = m + 1; else hi = m; }
    int start = lo;
    lo = 0; hi = N;
    while (lo < hi) { int m = (lo + hi) >> 1; if (arr[m] <= b) lo = m + 1; else hi = m; }
    g_seg[t * 2 + 0] = start;
    g_seg[t * 2 + 1] = lo;
}

__global__ void colmean_kernel(const float* __restrict__ x1, const float* __restrict__ x2, int N) {
    const float* x = blockIdx.x ? x2 : x1;
    int c = threadIdx.x;
    float s0 = 0.f, s1 = 0.f, s2 = 0.f, s3 = 0.f;
    int r = 0;
    for (; r + 3 < N; r += 4) {
        s0 += x[(size_t)(r + 0) * DD + c];
        s1 += x[(size_t)(r + 1) * DD + c];
        s2 += x[(size_t)(r + 2) * DD + c];
        s3 += x[(size_t)(r + 3) * DD + c];
    }
    for (; r < N; ++r) s0 += x[(size_t)r * DD + c];
    g_colmeans[blockIdx.x * DD + c] = (s0 + s1 + s2 + s3) * (1.f / (float)N);
}

__global__ void prep_all_kernel(const float* __restrict__ mW1, const float* __restrict__ mW2,
                                const float* __restrict__ uW1, const float* __restrict__ uW2) {
    int idx = blockIdx.x * 256 + threadIdx.x;
    if (idx < 131072) {
        int layer = idx >> 16;
        int e = idx & 65535;
        int k = e >> 8, n = e & 255;
        const float* W = layer ? mW2 : mW1;
        *(__half*)(g_wtile[layer][k >> 5] + (size_t)n * 80 + (size_t)(k & 31) * 2) =
            __float2half_rn(W[e]);
    } else if (idx < 262144) {
        int e = idx - 131072;
        int k = e >> 8, n = e & 255;
        *(__half*)(g_uw1[k >> 6] + (size_t)n * 144 + (size_t)(k & 63) * 2) =
            __float2half_rn(uW1[e]);
    } else {
        int e = idx - 262144;
        int k = e >> 7, n = e & 127;
        *(__half*)(g_uw2[k >> 6] + (size_t)n * 144 + (size_t)(k & 63) * 2) =
            __float2half_rn(uW2[e]);
    }
}

// ================= shared msg-style mma pieces (256 thr, occ 2, dbuf B) =================
#define MA_STRIDE 528
#define MOFF_A 0
#define MOFF_B0 33792
#define MOFF_B1 54272
#define MOFF_BIAS 74752
#define MOFF_ID 75776
#define MSG_SMEM2 76288

__device__ __forceinline__ void load_msg_b(uint32_t b_base, int tid, int layer, int s) {
    const unsigned char* hs = g_wtile[layer][s];
    #pragma unroll
    for (int t = 0; t < 5; ++t) {
        int i = tid + t * MTHR;
        cp_async16(b_base + i * 16, hs + i * 16);
    }
    cp_commit();
}

// convert 64 fp32 values into fp16 A tile at row r, col base cb
__device__ __forceinline__ void put64(char* smc, int r, int cb, const float v[64]) {
    #pragma unroll
    for (int b = 0; b < 8; ++b) {
        uint32_t h[4];
        #pragma unroll
        for (int q = 0; q < 4; ++q)
            h[q] = pk16(v[b * 8 + q * 2], v[b * 8 + q * 2 + 1]);
        *(uint4*)(smc + MOFF_A + r * MA_STRIDE + (cb + b * 8) * 2) =
            make_uint4(h[0], h[1], h[2], h[3]);
    }
}

__device__ __forceinline__ void gather64(char* smc, int r, int cb, const float* __restrict__ rowp) {
    float v[64];
    #pragma unroll
    for (int b = 0; b < 16; ++b) {
        float4 t = *(const float4*)(rowp + b * 4);
        v[b * 4 + 0] = t.x; v[b * 4 + 1] = t.y; v[b * 4 + 2] = t.z; v[b * 4 + 3] = t.w;
    }
    put64(smc, r, cb, v);
}

// one K=32 slice mma pass; warp tile 32 rows x 64 cols; single-term fp16
__device__ __forceinline__ void mma_slice(uint32_t sb, uint32_t b_base, int kbase,
                                          int wm, int wn, int lane, float acc[2][8][4]) {
    #pragma unroll
    for (int ks = 0; ks < 2; ++ks) {
        int kg = kbase + ks * 16;
        uint32_t ah[2][4];
        #pragma unroll
        for (int mt = 0; mt < 2; ++mt) {
            int row = wm * 32 + mt * 16 + (lane & 15);
            ldmx4(ah[mt], sb + MOFF_A + row * MA_STRIDE + (kg + (lane >> 4) * 8) * 2);
        }
        #pragma unroll
        for (int ntp = 0; ntp < 4; ++ntp) {
            int q = lane >> 3, rr = lane & 7;
            int n = wn * 64 + ntp * 16 + (q >> 1) * 8 + rr;
            uint32_t bh[4];
            ldmx4(bh, b_base + n * 80 + (ks * 16 + (q & 1) * 8) * 2);
            #pragma unroll
            for (int mt = 0; mt < 2; ++mt) {
                mma_f16(acc[mt][ntp * 2],     ah[mt], bh[0], bh[1]);
                mma_f16(acc[mt][ntp * 2 + 1], ah[mt], bh[2], bh[3]);
            }
        }
    }
}

// ================= pre kernel: P = x @ W1half per node =================
__global__ void __launch_bounds__(MTHR, 2)
pre_mma_kernel(const float* __restrict__ x1, const float* __restrict__ x2, int N) {
    int g = blockIdx.y >> 1, half = blockIdx.y & 1;
    const float* x = g ? x2 : x1;
    float* P = (half ? g_p2 : g_p1) + (size_t)g * N * HH;

    extern __shared__ char smc[];
    uint32_t sb = smem_u32(smc);
    uint32_t bbuf[2] = { sb + MOFF_B0, sb + MOFF_B1 };

    int tid = threadIdx.x, wid = tid >> 5, lane = tid & 31;
    int base = blockIdx.x * 64;
    int wm = wid & 1, wn = wid >> 1;
    int gr = lane >> 2, gc = lane & 3;

    load_msg_b(bbuf[0], tid, 0, half * 4);
    if (tid < 128) {
        int r = tid >> 1, seg = tid & 1;
        int node = base + r; if (node >= N) node = N - 1;
        gather64(smc, r, seg * 64, x + (size_t)node * DD + seg * 64);
    }
    cp_wait<0>();
    __syncthreads();

    float acc[2][8][4];
    #pragma unroll
    for (int mt = 0; mt < 2; ++mt)
        #pragma unroll
        for (int nt = 0; nt < 8; ++nt)
            #pragma unroll
            for (int q = 0; q < 4; ++q) acc[mt][nt][q] = 0.f;

    for (int s = 0; s < 4; ++s) {
        if (s + 1 < 4) load_msg_b(bbuf[(s + 1) & 1], tid, 0, half * 4 + s + 1);
        mma_slice(sb, bbuf[s & 1], s * 32, wm, wn, lane, acc);
        if (s + 1 < 4) cp_wait<0>();
        __syncthreads();
    }

    #pragma unroll
    for (int mt = 0; mt < 2; ++mt) {
        int r0 = wm * 32 + mt * 16 + gr;
        int r1 = r0 + 8;
        int n0 = base + r0, n1 = base + r1;
        #pragma unroll
        for (int nt = 0; nt < 8; ++nt) {
            int col = wn * 64 + nt * 8 + 2 * gc;
            if (n0 < N) *(float2*)(P + (size_t)n0 * HH + col) = make_float2(acc[mt][nt][0], acc[mt][nt][1]);
            if (n1 < N) *(float2*)(P + (size_t)n1 * HH + col) = make_float2(acc[mt][nt][2], acc[mt][nt][3]);
        }
    }
}

// ================= msg kernel: H = relu(P1[src]+P2[tgt]+b1); M = H@W2; scatter =================
__global__ void __launch_bounds__(MTHR, 2)
msg_mma_kernel(const int* __restrict__ ei1, const int* __restrict__ ei2,
               const float* __restrict__ b1, const float* __restrict__ b2,
               int N, int E) {
    int g = blockIdx.y;
    const int* ei = g ? ei2 : ei1;
    float* messages = g_messages + (size_t)g * N * HH;
    const float* P1 = g_p1 + (size_t)g * N * HH;
    const float* P2 = g_p2 + (size_t)g * N * HH;

    extern __shared__ char smc[];
    uint32_t sb = smem_u32(smc);
    uint32_t bbuf[2] = { sb + MOFF_B0, sb + MOFF_B1 };
    float* b1s = (float*)(smc + MOFF_BIAS);
    int* s_src = (int*)(smc + MOFF_ID);
    int* s_tgt = s_src + 64;

    int tid = threadIdx.x, wid = tid >> 5, lane = tid & 31;
    int base = blockIdx.x * 64;

    b1s[tid] = b1[tid];
    if (tid < 64) {
        int e = base + tid;
        s_tgt[tid] = (e < E) ? ei[e] : 0;
        s_src[tid] = (e < E) ? ei[E + e] : 0;
    }
    __syncthreads();

    int wm = wid & 1, wn = wid >> 1;
    int gr = lane >> 2, gc = lane & 3;

    load_msg_b(bbuf[0], tid, 1, 0);
    {
        int r = tid >> 2, seg = tid & 3;
        const float* p1r = P1 + (size_t)s_src[r] * HH + seg * 64;
        const float* p2r = P2 + (size_t)s_tgt[r] * HH + seg * 64;
        const float* bb = b1s + seg * 64;
        float v[64];
        #pragma unroll
        for (int b = 0; b < 16; ++b) {
            float4 u = *(const float4*)(p1r + b * 4);
            float4 w = *(const float4*)(p2r + b * 4);
            float4 bv = *(const float4*)(bb + b * 4);
            v[b * 4 + 0] = fmaxf(u.x + w.x + bv.x, 0.f);
            v[b * 4 + 1] = fmaxf(u.y + w.y + bv.y, 0.f);
            v[b * 4 + 2] = fmaxf(u.z + w.z + bv.z, 0.f);
            v[b * 4 + 3] = fmaxf(u.w + w.w + bv.w, 0.f);
        }
        put64(smc, r, seg * 64, v);
    }
    cp_wait<0>();
    __syncthreads();

    float acc[2][8][4];
    #pragma unroll
    for (int mt = 0; mt < 2; ++mt)
        #pragma unroll
        for (int nt = 0; nt < 8; ++nt)
            #pragma unroll
            for (int q = 0; q < 4; ++q) acc[mt][nt][q] = 0.f;

    for (int s = 0; s < 8; ++s) {
        if (s + 1 < 8) load_msg_b(bbuf[(s + 1) & 1], tid, 1, s + 1);
        mma_slice(sb, bbuf[s & 1], s * 32, wm, wn, lane, acc);
        if (s + 1 < 8) cp_wait<0>();
        __syncthreads();
    }

    #pragma unroll
    for (int mt = 0; mt < 2; ++mt) {
        int r0 = wm * 32 + mt * 16 + gr;
        int r1 = r0 + 8;
        bool v0 = (base + r0) < E, v1 = (base + r1) < E;
        float* m0 = messages + (size_t)s_tgt[r0] * HH;
        float* m1 = messages + (size_t)s_tgt[r1] * HH;
        #pragma unroll
        for (int nt = 0; nt < 8; ++nt) {
            int col = wn * 64 + nt * 8 + 2 * gc;
            float2 bv = *(const float2*)(b2 + col);
            if (v0) red_add_v2(m0 + col, acc[mt][nt][0] + bv.x, acc[mt][nt][1] + bv.y);
            if (v1) red_add_v2(m1 + col, acc[mt][nt][2] + bv.x, acc[mt][nt][3] + bv.y);
        }
    }
}

// ================= upd kernel (512 thr, occ 2, fp16) =================
#define OFF_A 0
#define OFF_B 17408
#define BBUF_BYTES 36864
#define UPD_SMEM (17408 + 2*36864)   // 91136

__device__ __forceinline__ void gather_a(char* smc, int r, int seg, const float* __restrict__ rowp) {
    const float4* row = (const float4*)(rowp + seg * 16);
    uint32_t h[8];
    #pragma unroll
    for (int q = 0; q < 4; ++q) {
        float4 v = row[q];
        h[q * 2 + 0] = pk16(v.x, v.y);
        h[q * 2 + 1] = pk16(v.z, v.w);
    }
    uint4* d = (uint4*)(smc + OFF_A + r * 272 + seg * 32);
    d[0] = make_uint4(h[0], h[1], h[2], h[3]);
    d[1] = make_uint4(h[4], h[5], h[6], h[7]);
}

template<int NT>
__device__ __forceinline__ void mma_hc(uint32_t sb, int a_k0, uint32_t b_base,
                                       int wm, int wn, int lane, float acc[2][NT][4]) {
    #pragma unroll
    for (int ks = 0; ks < 4; ++ks) {
        int k0 = ks * 16;
        uint32_t ah[2][4];
        #pragma unroll
        for (int mt = 0; mt < 2; ++mt) {
            int row = wm * 32 + mt * 16 + (lane & 15);
            ldmx4(ah[mt], sb + OFF_A + row * 272 + (a_k0 + k0 + (lane >> 4) * 8) * 2);
        }
        uint32_t bh[(NT + 1) / 2][4];
        #pragma unroll
        for (int ntp = 0; ntp < (NT + 1) / 2; ++ntp) {
            int q = lane >> 3, rr = lane & 7;
            int n = wn * (NT * 8) + ntp * 16 + (q >> 1) * 8 + rr;
            int kk = k0 + (q & 1) * 8;
            ldmx4(bh[ntp], b_base + n * 144 + kk * 2);
        }
        #pragma unroll
        for (int mt = 0; mt < 2; ++mt)
            #pragma unroll
            for (int nt = 0; nt < NT; ++nt) {
                int p = nt >> 1, h2 = (nt & 1) * 2;
                mma_f16(acc[mt][nt], ah[mt], bh[p][h2], bh[p][h2 + 1]);
            }
    }
}

__device__ __forceinline__ void load_b_hc(uint32_t b_base, int tid,
                                          const unsigned char* hsrc, int lines) {
    for (int t = tid; t < lines; t += NTHR)
        cp_async16(b_base + t * 16, hsrc + t * 16);
    cp_commit();
}

__global__ void __launch_bounds__(NTHR, 2)
upd_mma_kernel(const float* __restrict__ x1, const float* __restrict__ x2,
               const float* __restrict__ b1u, const float* __restrict__ b2u,
               float* __restrict__ out, int N) {
    int g = blockIdx.y;
    const float* x = g ? x2 : x1;
    const float* messages = g_messages + (size_t)g * N * HH;
    const float* att = g_att + (size_t)g * N * DD;
    float* o = out + (size_t)g * N * DD;

    extern __shared__ char smc[];
    uint32_t sb = smem_u32(smc);

    int tid = threadIdx.x, wid = tid >> 5, lane = tid & 31;
    int base = blockIdx.x * 64;
    int wm = wid & 1, wn = wid >> 1;
    int gr = lane >> 2, gc = lane & 3;
    int r = tid >> 3, seg = tid & 7;
    uint32_t bbuf[2] = { sb + OFF_B, sb + OFF_B + BBUF_BYTES };

    int node = base + r;
    if (node >= N) node = N - 1;
    const float* srcs[4] = {
        messages + (size_t)node * HH,
        messages + (size_t)node * HH + 128,
        att + (size_t)node * DD,
        x + (size_t)node * DD
    };

    float acc[2][4][4];
    #pragma unroll
    for (int mt = 0; mt < 2; ++mt)
        #pragma unroll
        for (int nt = 0; nt < 4; ++nt)
            #pragma unroll
            for (int q = 0; q < 4; ++q) acc[mt][nt][q] = 0.f;

    load_b_hc(bbuf[0], tid, g_uw1[0], 2304);
    gather_a(smc, r, seg, srcs[0]);
    load_b_hc(bbuf[1], tid, g_uw1[1], 2304);
    cp_wait<1>();
    __syncthreads();

    #pragma unroll
    for (int hc = 0; hc < 8; ++hc) {
        mma_hc<4>(sb, (hc & 1) * 64, bbuf[hc & 1], wm, wn, lane, acc);
        __syncthreads();
        if ((hc & 1) == 1 && hc < 7) gather_a(smc, r, seg, srcs[(hc + 1) >> 1]);
        if (hc + 2 < 8) {
            load_b_hc(bbuf[hc & 1], tid, g_uw1[hc + 2], 2304);
            cp_wait<1>();
        } else if (hc + 1 < 8) {
            cp_wait<0>();
        }
        __syncthreads();
    }

    uint32_t hh[2][4][2];
    #pragma unroll
    for (int nt = 0; nt < 4; ++nt) {
        int col = wn * 32 + nt * 8 + 2 * gc;
        float2 bv = *(const float2*)(b1u + col);
        #pragma unroll
        for (int mt = 0; mt < 2; ++mt) {
            float f0 = fmaxf(acc[mt][nt][0] + bv.x, 0.f);
            float f1 = fmaxf(acc[mt][nt][1] + bv.y, 0.f);
            float f2 = fmaxf(acc[mt][nt][2] + bv.x, 0.f);
            float f3 = fmaxf(acc[mt][nt][3] + bv.y, 0.f);
            hh[mt][nt][0] = pk16(f0, f1);
            hh[mt][nt][1] = pk16(f2, f3);
            acc[mt][nt][0] = acc[mt][nt][1] = acc[mt][nt][2] = acc[mt][nt][3] = 0.f;
        }
    }

    int wm2 = wid & 1, wn2 = wid >> 1;
    float (*acc2)[2][4] = (float (*)[2][4])acc;

    load_b_hc(bbuf[0], tid, g_uw2[0], 1152);
    if (wn < 4) {
        #pragma unroll
        for (int mt = 0; mt < 2; ++mt) {
            int rr = wm * 32 + mt * 16 + gr;
            #pragma unroll
            for (int nt = 0; nt < 4; ++nt) {
                int cc = wn * 32 + nt * 8 + 2 * gc;
                *(uint32_t*)(smc + OFF_A + rr * 272 + cc * 2)       = hh[mt][nt][0];
                *(uint32_t*)(smc + OFF_A + (rr + 8) * 272 + cc * 2) = hh[mt][nt][1];
            }
        }
    }
    load_b_hc(bbuf[1], tid, g_uw2[1], 1152);
    cp_wait<1>();
    __syncthreads();

    #pragma unroll
    for (int hc = 0; hc < 4; ++hc) {
        mma_hc<2>(sb, (hc & 1) * 64, bbuf[hc & 1], wm2, wn2, lane, acc2);
        __syncthreads();
        if (hc == 1 && wn >= 4) {
            #pragma unroll
            for (int mt = 0; mt < 2; ++mt) {
                int rr = wm * 32 + mt * 16 + gr;
                #pragma unroll
                for (int nt = 0; nt < 4; ++nt) {
                    int cc = (wn & 3) * 32 + nt * 8 + 2 * gc;
                    *(uint32_t*)(smc + OFF_A + rr * 272 + cc * 2)       = hh[mt][nt][0];
                    *(uint32_t*)(smc + OFF_A + (rr + 8) * 272 + cc * 2) = hh[mt][nt][1];
                }
            }
        }
        if (hc + 2 < 4) {
            load_b_hc(bbuf[hc & 1], tid, g_uw2[hc + 2], 1152);
            cp_wait<1>();
        } else if (hc + 1 < 4) {
            cp_wait<0>();
        }
        __syncthreads();
    }

    #pragma unroll
    for (int mt = 0; mt < 2; ++mt) {
        int r0 = wm2 * 32 + mt * 16 + gr;
        int r1 = r0 + 8;
        int n0 = base + r0, n1 = base + r1;
        #pragma unroll
        for (int nt = 0; nt < 2; ++nt) {
            int col = wn2 * 16 + nt * 8 + 2 * gc;
            float2 bv = *(const float2*)(b2u + col);
            if (n0 < N) {
                float2 xv = *(const float2*)(x + (size_t)n0 * DD + col);
                float2 rr;
                rr.x = acc2[mt][nt][0] + bv.x + xv.x;
                rr.y = acc2[mt][nt][1] + bv.y + xv.y;
                *(float2*)(o + (size_t)n0 * DD + col) = rr;
            }
            if (n1 < N) {
                float2 xv = *(const float2*)(x + (size_t)n1 * DD + col);
                float2 rr;
                rr.x = acc2[mt][nt][2] + bv.x + xv.x;
                rr.y = acc2[mt][nt][3] + bv.y + xv.y;
                *(float2*)(o + (size_t)n1 * DD + col) = rr;
            }
        }
    }
}

// ---------------- block-diagonal cross attention (round-13 proven) ----------------
#define ATT_MAXC 320
#define ATT_S 129
#define ATT_SBOFF (ATT_MAXC * ATT_S)
#define ATT_RBOFF (ATT_SBOFF + 8 * ATT_MAXC)
#define ATT_SMEM ((ATT_RBOFF + 8 * 132) * 4)

__global__ void attn_kernel(const float* __restrict__ x1,
                            const float* __restrict__ x2, int N) {
    extern __shared__ float asm_[];
    float* colsm = asm_;
    int b = blockIdx.x;
    int dir = blockIdx.y;
    const float* rowsrc = dir ? x2 : x1;
    const float* colsrc = dir ? x1 : x2;
    float* att = g_att + (size_t)dir * N * DD;
    int rs = g_seg[(dir * NB + b) * 2 + 0];
    int re = g_seg[(dir * NB + b) * 2 + 1];
    int cs = g_seg[((1 - dir) * NB + b) * 2 + 0];
    int ce = g_seg[((1 - dir) * NB + b) * 2 + 1];
    const float* mean = g_colmeans + (1 - dir) * DD;
    int nc = ce - cs;

    int warp = threadIdx.x >> 5, lane = threadIdx.x & 31;
    float* sbuf = asm_ + ATT_SBOFF + warp * ATT_MAXC;
    float* rowb = asm_ + ATT_RBOFF + warp * 132;

    if (nc == 0) {
        for (int i = rs + warp; i < re; i += 8) {
            float4 a = *(const float4*)(rowsrc + (size_t)i * DD + lane * 4);
            float4 mv = *(const float4*)(mean + lane * 4);
            float4 res;
            res.x = a.x - mv.x; res.y = a.y - mv.y;
            res.z = a.z - mv.z; res.w = a.w - mv.w;
            *(float4*)(att + (size_t)i * DD + lane * 4) = res;
        }
        return;
    }

    if (nc <= ATT_MAXC) {
        for (int idx = threadIdx.x; idx < nc * DD; idx += 256) {
            int j = idx >> 7, k = idx & 127;
            colsm[j * ATT_S + k] = colsrc[(size_t)(cs + j) * DD + k];
        }
        __syncthreads();

        int npass = (nc + 31) >> 5;
        for (int i = rs + warp; i < re; i += 8) {
            float4 a4 = *(const float4*)(rowsrc + (size_t)i * DD + lane * 4);
            *(float4*)(rowb + lane * 4) = a4;
            __syncwarp();

            float m = -3.4e38f;
            for (int cb = 0; cb < npass; ++cb) {
                int j = cb * 32 + lane;
                float s = -3.4e38f;
                if (j < nc) {
                    s = 0.f;
                    const float* cp = colsm + j * ATT_S;
                    #pragma unroll 8
                    for (int k = 0; k < DD; ++k) s = fmaf(rowb[k], cp[k], s);
                    sbuf[j] = s;
                }
                m = fmaxf(m, s);
            }
            #pragma unroll
            for (int o = 16; o; o >>= 1) m = fmaxf(m, __shfl_xor_sync(0xffffffffu, m, o));

            float se = 0.f;
            for (int cb = 0; cb < npass; ++cb) {
                int j = cb * 32 + lane;
                if (j < nc) {
                    float w = __expf(sbuf[j] - m);
                    sbuf[j] = w;
                    se += w;
                }
            }
            #pragma unroll
            for (int o = 16; o; o >>= 1) se += __shfl_xor_sync(0xffffffffu, se, o);
            float inv = 1.f / se;
            __syncwarp();

            float acc0 = 0.f, acc1 = 0.f, acc2 = 0.f, acc3 = 0.f;
            for (int j = 0; j < nc; ++j) {
                float w = sbuf[j];
                const float* cp = colsm + j * ATT_S + lane;
                acc0 = fmaf(w, cp[0],  acc0);
                acc1 = fmaf(w, cp[32], acc1);
                acc2 = fmaf(w, cp[64], acc2);
                acc3 = fmaf(w, cp[96], acc3);
            }
            float* ar = att + (size_t)i * DD;
            ar[lane]      = rowb[lane]      - acc0 * inv;
            ar[lane + 32] = rowb[lane + 32] - acc1 * inv;
            ar[lane + 64] = rowb[lane + 64] - acc2 * inv;
            ar[lane + 96] = rowb[lane + 96] - acc3 * inv;
            __syncwarp();
        }
    } else {
        for (int i = rs + warp; i < re; i += 8) {
            float4 a = *(const float4*)(rowsrc + (size_t)i * DD + lane * 4);
            float m = -3.4e38f;
            for (int j = cs; j < ce; ++j) {
                float4 bv = *(const float4*)(colsrc + (size_t)j * DD + lane * 4);
                float d = a.x * bv.x + a.y * bv.y + a.z * bv.z + a.w * bv.w;
                #pragma unroll
                for (int o = 16; o; o >>= 1) d += __shfl_xor_sync(0xffffffffu, d, o);
                m = fmaxf(m, d);
            }
            float se = 0.f;
            float4 acc = make_float4(0.f, 0.f, 0.f, 0.f);
            for (int j = cs; j < ce; ++j) {
                float4 bv = *(const float4*)(colsrc + (size_t)j * DD + lane * 4);
                float d = a.x * bv.x + a.y * bv.y + a.z * bv.z + a.w * bv.w;
                #pragma unroll
                for (int o = 16; o; o >>= 1) d += __shfl_xor_sync(0xffffffffu, d, o);
                float w = __expf(d - m);
                se += w;
                acc.x = fmaf(w, bv.x, acc.x);
                acc.y = fmaf(w, bv.y, acc.y);
                acc.z = fmaf(w, bv.z, acc.z);
                acc.w = fmaf(w, bv.w, acc.w);
            }
            float inv = 1.f / se;
            float4 res;
            res.x = a.x - acc.x * inv; res.y = a.y - acc.y * inv;
            res.z = a.z - acc.z * inv; res.w = a.w - acc.w * inv;
            *(float4*)(att + (size_t)i * DD + lane * 4) = res;
        }
    }
}

// ---------------- launcher ----------------
extern "C" void kernel_launch(void* const* d_in, const int* in_sizes, int n_in,
                              void* d_out, int out_size) {
    const float* x1   = (const float*)d_in[0];
    const int*   ei1  = (const int*)d_in[1];
    const int*   bat1 = (const int*)d_in[2];
    const float* x2   = (const float*)d_in[3];
    const int*   ei2  = (const int*)d_in[4];
    const int*   bat2 = (const int*)d_in[5];
    const float* mW1 = (const float*)d_in[6];
    const float* mb1 = (const float*)d_in[7];
    const float* mW2 = (const float*)d_in[8];
    const float* mb2 = (const float*)d_in[9];
    const float* uW1 = (const float*)d_in[10];
    const float* ub1 = (const float*)d_in[11];
    const float* uW2 = (const float*)d_in[12];
    const float* ub2 = (const float*)d_in[13];
    float* out = (float*)d_out;

    int N = in_sizes[2];
    int E = in_sizes[1] / 2;

    cudaFuncSetAttribute(pre_mma_kernel, cudaFuncAttributeMaxDynamicSharedMemorySize, MSG_SMEM2);
    cudaFuncSetAttribute(msg_mma_kernel, cudaFuncAttributeMaxDynamicSharedMemorySize, MSG_SMEM2);
    cudaFuncSetAttribute(upd_mma_kernel, cudaFuncAttributeMaxDynamicSharedMemorySize, UPD_SMEM);
    cudaFuncSetAttribute(attn_kernel, cudaFuncAttributeMaxDynamicSharedMemorySize, ATT_SMEM);

    int zn4 = 2 * N * HH / 4;
    zero_msgs_kernel<<<(zn4 + 255) / 256, 256>>>(zn4);
    seg_kernel<<<1, 128>>>(bat1, bat2, N);
    colmean_kernel<<<2, DD>>>(x1, x2, N);
    prep_all_kernel<<<1152, 256>>>(mW1, mW2, uW1, uW2);

    dim3 pgrid((N + 63) / 64, 4);
    pre_mma_kernel<<<pgrid, MTHR, MSG_SMEM2>>>(x1, x2, N);

    dim3 mgrid((E + 63) / 64, 2);
    msg_mma_kernel<<<mgrid, MTHR, MSG_SMEM2>>>(ei1, ei2, mb1, mb2, N, E);

    attn_kernel<<<dim3(NB, 2), 256, ATT_SMEM>>>(x1, x2, N);

    dim3 ugrid((N + 63) / 64, 2);
    upd_mma_kernel<<<ugrid, NTHR, UPD_SMEM>>>(x1, x2, ub1, ub2, out, N);
}